// round 1
// baseline (speedup 1.0000x reference)
#include <cuda_runtime.h>
#include <math.h>
#include <stdint.h>

#define BB 64
#define NN 1024
#define DD 512
#define CC 512
#define KTOP 16
#define INV_TEMP (1.0f/0.07f)

// ---------------- scratch (device globals: no allocations allowed) ----------
__device__ float g_aff[(size_t)BB * CC * NN];   // [b][c][n]  (transposed for topk)
__device__ float g_rnp[BB * NN];                // 1/max(||patch||, eps)
__device__ float g_rnt[CC];                     // 1/max(||text||, eps)
__device__ float g_rnc[BB];                     // 1/max(||cls||, eps)

// ---------------- f32x2 helpers (FFMA2 — PTX only, ptxas won't auto-fuse) ---
static __device__ __forceinline__ unsigned long long pk2(float x, float y){
    unsigned long long r;
    asm("mov.b64 %0, {%1,%2};" : "=l"(r) : "f"(x), "f"(y));
    return r;
}
static __device__ __forceinline__ void upk2(unsigned long long d, float &x, float &y){
    asm("mov.b64 {%0,%1}, %2;" : "=f"(x), "=f"(y) : "l"(d));
}
static __device__ __forceinline__ void fma2(unsigned long long &d,
                                            unsigned long long a,
                                            unsigned long long b){
    asm("fma.rn.f32x2 %0, %1, %2, %0;" : "+l"(d) : "l"(a), "l"(b));
}

// ---------------- kernel 1: row L2 norms (warp per 512-float row) ----------
__global__ void norms_kernel(const float* __restrict__ vcls,
                             const float* __restrict__ vp,
                             const float* __restrict__ text){
    int w    = (blockIdx.x * blockDim.x + threadIdx.x) >> 5;
    int lane = threadIdx.x & 31;
    const int NWARPS = BB*NN + CC + BB;   // 66112
    if (w >= NWARPS) return;
    const float* src; float* dst;
    if (w < BB*NN)            { src = vp   + (size_t)w * DD;               dst = g_rnp + w; }
    else if (w < BB*NN + CC)  { src = text + (size_t)(w - BB*NN) * DD;     dst = g_rnt + (w - BB*NN); }
    else                      { src = vcls + (size_t)(w - BB*NN - CC) * DD; dst = g_rnc + (w - BB*NN - CC); }
    float ss = 0.f;
    #pragma unroll
    for (int j = 0; j < 4; j++){
        float4 v = *reinterpret_cast<const float4*>(src + ((j*32 + lane) << 2));
        ss += v.x*v.x + v.y*v.y + v.z*v.z + v.w*v.w;
    }
    #pragma unroll
    for (int off = 16; off; off >>= 1) ss += __shfl_xor_sync(0xffffffffu, ss, off);
    if (lane == 0) *dst = 1.0f / fmaxf(sqrtf(ss), 1e-12f);
}

// ---------------- kernel 2: global affinity, writes 0.3*softmax ------------
__global__ __launch_bounds__(512) void affg_kernel(const float* __restrict__ vcls,
                                                   const float* __restrict__ text,
                                                   float* __restrict__ out){
    __shared__ float sv[DD];
    __shared__ float red[16];
    int b = blockIdx.x, tid = threadIdx.x;
    sv[tid] = vcls[b*DD + tid];
    __syncthreads();
    const float* t = text + (size_t)tid * DD;
    float dot = 0.f;
    #pragma unroll 4
    for (int k = 0; k < DD; k += 4){
        float4 v = *reinterpret_cast<const float4*>(t + k);
        dot += v.x*sv[k] + v.y*sv[k+1] + v.z*sv[k+2] + v.w*sv[k+3];
    }
    float logit = dot * g_rnc[b] * g_rnt[tid] * INV_TEMP;
    int lane = tid & 31, wid = tid >> 5;
    float m = logit;
    #pragma unroll
    for (int off = 16; off; off >>= 1) m = fmaxf(m, __shfl_xor_sync(0xffffffffu, m, off));
    if (lane == 0) red[wid] = m;
    __syncthreads();
    float bm = red[0];
    #pragma unroll
    for (int i = 1; i < 16; i++) bm = fmaxf(bm, red[i]);
    __syncthreads();
    float e = __expf(logit - bm);
    float s = e;
    #pragma unroll
    for (int off = 16; off; off >>= 1) s += __shfl_xor_sync(0xffffffffu, s, off);
    if (lane == 0) red[wid] = s;
    __syncthreads();
    float bs = 0.f;
    #pragma unroll
    for (int i = 0; i < 16; i++) bs += red[i];
    out[b*CC + tid] = 0.3f * e / bs;
}

// ---------------- kernel 3: main GEMM + fused softmax + transposed write ----
// block: (n-tile of 64 patches) x (all 512 classes), 512 threads
// thread: 8 m-rows (mg=tid/64) x 8 classes (ng=tid%64: c = ng*4 + jj*256 + t)
__global__ __launch_bounds__(512, 1) void gemm_softmax_kernel(const float* __restrict__ vp,
                                                              const float* __restrict__ text){
    __shared__ __align__(16) float As[16][68];    // padded: conflict-light stores
    __shared__ __align__(16) float Bs[16][516];   // padded: conflict-free f4 reads
    __shared__ float s_rnp[64];
    __shared__ float sred[2][64];

    const int b  = blockIdx.y;
    const int nx = blockIdx.x;
    const int tid  = threadIdx.x;
    const int mg   = tid >> 6;      // 0..7
    const int ng   = tid & 63;      // 0..63
    const int w2   = ng >> 5;       // which of the 2 warps sharing these m-rows
    const int lane = tid & 31;

    const float* A = vp + ((size_t)b * NN + (size_t)nx * 64) * DD;
    if (tid < 64) s_rnp[tid] = g_rnp[b*NN + nx*64 + tid];

    unsigned long long acc[8][4];
    #pragma unroll
    for (int i = 0; i < 8; i++)
        #pragma unroll
        for (int j = 0; j < 4; j++) acc[i][j] = 0ULL;

    const int arow = tid >> 3;        // 0..63
    const int akk  = (tid & 7) * 2;   // 0,2,..,14

    for (int kt = 0; kt < DD/16; ++kt){
        __syncthreads();
        {   // A tile: 64 rows x 16 k
            float2 v = *reinterpret_cast<const float2*>(A + (size_t)arow*DD + kt*16 + akk);
            As[akk  ][arow] = v.x;
            As[akk+1][arow] = v.y;
        }
        #pragma unroll
        for (int i = 0; i < 4; i++){  // B tile: 512 classes x 16 k
            int f  = tid + i*512;
            int c  = f >> 2;
            int k4 = (f & 3) << 2;
            float4 v = *reinterpret_cast<const float4*>(text + (size_t)c*DD + kt*16 + k4);
            Bs[k4  ][c] = v.x;
            Bs[k4+1][c] = v.y;
            Bs[k4+2][c] = v.z;
            Bs[k4+3][c] = v.w;
        }
        __syncthreads();
        #pragma unroll
        for (int kk = 0; kk < 16; kk++){
            float4 a0 = *reinterpret_cast<const float4*>(&As[kk][mg*8]);
            float4 a1 = *reinterpret_cast<const float4*>(&As[kk][mg*8 + 4]);
            float4 b0 = *reinterpret_cast<const float4*>(&Bs[kk][ng*4]);
            float4 b1 = *reinterpret_cast<const float4*>(&Bs[kk][ng*4 + 256]);
            unsigned long long bp0 = pk2(b0.x, b0.y), bp1 = pk2(b0.z, b0.w);
            unsigned long long bp2 = pk2(b1.x, b1.y), bp3 = pk2(b1.z, b1.w);
            float av[8] = {a0.x,a0.y,a0.z,a0.w,a1.x,a1.y,a1.z,a1.w};
            #pragma unroll
            for (int mm = 0; mm < 8; mm++){
                unsigned long long ap = pk2(av[mm], av[mm]);
                fma2(acc[mm][0], ap, bp0);
                fma2(acc[mm][1], ap, bp1);
                fma2(acc[mm][2], ap, bp2);
                fma2(acc[mm][3], ap, bp3);
            }
        }
    }

    // ---- epilogue: scale -> softmax over c (64 threads = 2 warps share rows)
    float4 rt0 = *reinterpret_cast<const float4*>(&g_rnt[ng*4]);
    float4 rt1 = *reinterpret_cast<const float4*>(&g_rnt[ng*4 + 256]);
    float rt[8] = {rt0.x,rt0.y,rt0.z,rt0.w,rt1.x,rt1.y,rt1.z,rt1.w};

    float f[8][8];
    float rmax[8];
    #pragma unroll
    for (int mm = 0; mm < 8; mm++){
        float rp = s_rnp[mg*8 + mm] * INV_TEMP;
        #pragma unroll
        for (int p = 0; p < 4; p++) upk2(acc[mm][p], f[mm][2*p], f[mm][2*p+1]);
        float mx = -3.0e38f;
        #pragma unroll
        for (int q = 0; q < 8; q++){
            float v = f[mm][q] * rp * rt[q];
            f[mm][q] = v;
            mx = fmaxf(mx, v);
        }
        #pragma unroll
        for (int off = 16; off; off >>= 1) mx = fmaxf(mx, __shfl_xor_sync(0xffffffffu, mx, off));
        rmax[mm] = mx;
    }
    if (lane == 0){
        #pragma unroll
        for (int mm = 0; mm < 8; mm++) sred[w2][mg*8 + mm] = rmax[mm];
    }
    __syncthreads();
    float gmax[8];
    #pragma unroll
    for (int mm = 0; mm < 8; mm++) gmax[mm] = fmaxf(sred[0][mg*8+mm], sred[1][mg*8+mm]);
    __syncthreads();
    float rsum[8];
    #pragma unroll
    for (int mm = 0; mm < 8; mm++){
        float s = 0.f;
        #pragma unroll
        for (int q = 0; q < 8; q++){
            float e = __expf(f[mm][q] - gmax[mm]);
            f[mm][q] = e;
            s += e;
        }
        #pragma unroll
        for (int off = 16; off; off >>= 1) s += __shfl_xor_sync(0xffffffffu, s, off);
        rsum[mm] = s;
    }
    if (lane == 0){
        #pragma unroll
        for (int mm = 0; mm < 8; mm++) sred[w2][mg*8 + mm] = rsum[mm];
    }
    __syncthreads();
    float inv[8];
    #pragma unroll
    for (int mm = 0; mm < 8; mm++) inv[mm] = 1.0f / (sred[0][mg*8+mm] + sred[1][mg*8+mm]);

    // ---- transposed write: g_aff[b][c][n], 8 contiguous n per (thread,c)
    float* dst = g_aff + (size_t)b * CC * NN + (size_t)nx * 64 + (size_t)mg * 8;
    #pragma unroll
    for (int q = 0; q < 8; q++){
        int c = ng*4 + (q >> 2)*256 + (q & 3);
        float4 o0 = make_float4(f[0][q]*inv[0], f[1][q]*inv[1], f[2][q]*inv[2], f[3][q]*inv[3]);
        float4 o1 = make_float4(f[4][q]*inv[4], f[5][q]*inv[5], f[6][q]*inv[6], f[7][q]*inv[7]);
        *reinterpret_cast<float4*>(dst + (size_t)c*NN)     = o0;
        *reinterpret_cast<float4*>(dst + (size_t)c*NN + 4) = o1;
    }
}

// ---------------- kernel 4: top-16 over N per (b,c), blend into out --------
__global__ void topk_kernel(float* __restrict__ out){
    int w    = (blockIdx.x * blockDim.x + threadIdx.x) >> 5;  // b*512 + c
    int lane = threadIdx.x & 31;
    if (w >= BB*CC) return;
    const float* p = g_aff + (size_t)w * NN;
    float v[32];
    #pragma unroll
    for (int j = 0; j < 32; j++) v[j] = p[j*32 + lane];
    float lm = -1e30f; int li = 0;
    #pragma unroll
    for (int j = 0; j < 32; j++) if (v[j] > lm){ lm = v[j]; li = j; }
    float sum = 0.f;
    for (int it = 0; it < KTOP; ++it){
        float m = lm; int src = lane;
        #pragma unroll
        for (int off = 16; off; off >>= 1){
            float om = __shfl_xor_sync(0xffffffffu, m,   off);
            int   os = __shfl_xor_sync(0xffffffffu, src, off);
            if (om > m || (om == m && os < src)){ m = om; src = os; }
        }
        sum += m;
        if (lane == src){
            #pragma unroll
            for (int j = 0; j < 32; j++) if (j == li) v[j] = -1e30f;
            lm = -1e30f; li = 0;
            #pragma unroll
            for (int j = 0; j < 32; j++) if (v[j] > lm){ lm = v[j]; li = j; }
        }
    }
    if (lane == 0) out[w] += 0.7f * (sum * (1.0f/(float)KTOP));
}

// ---------------- launch ----------------------------------------------------
extern "C" void kernel_launch(void* const* d_in, const int* in_sizes, int n_in,
                              void* d_out, int out_size){
    const float* vcls = nullptr;
    const float* vp   = nullptr;
    const float* text = nullptr;
    for (int i = 0; i < n_in; i++){
        if      (in_sizes[i] == BB*DD)            vcls = (const float*)d_in[i];
        else if (in_sizes[i] == BB*NN*DD)         vp   = (const float*)d_in[i];
        else if (in_sizes[i] == CC*DD)            text = (const float*)d_in[i];
    }
    float* out = (float*)d_out;

    const int nwarps = BB*NN + CC + BB;             // 66112
    norms_kernel<<<(nwarps + 7)/8, 256>>>(vcls, vp, text);
    affg_kernel<<<BB, 512>>>(vcls, text, out);
    gemm_softmax_kernel<<<dim3(NN/64, BB), 512>>>(vp, text);
    topk_kernel<<<(BB*CC + 7)/8, 256>>>(out);
}

// round 2
// speedup vs baseline: 1.0014x; 1.0014x over previous
#include <cuda_runtime.h>
#include <math.h>
#include <stdint.h>

#define BB 64
#define NN 1024
#define DD 512
#define CC 512
#define KTOP 16
#define INV_TEMP (1.0f/0.07f)

// ---------------- scratch (device globals: no allocations allowed) ----------
__device__ float g_aff[(size_t)BB * CC * NN];   // [b][c][n]  (transposed for topk)
__device__ float g_rnp[BB * NN];                // 1/max(||patch||, eps)
__device__ float g_rnt[CC];                     // 1/max(||text||, eps)
__device__ float g_rnc[BB];                     // 1/max(||cls||, eps)

// ---------------- f32x2 helpers (FFMA2 — PTX only, ptxas won't auto-fuse) ---
static __device__ __forceinline__ unsigned long long pk2(float x, float y){
    unsigned long long r;
    asm("mov.b64 %0, {%1,%2};" : "=l"(r) : "f"(x), "f"(y));
    return r;
}
static __device__ __forceinline__ void upk2(unsigned long long d, float &x, float &y){
    asm("mov.b64 {%0,%1}, %2;" : "=f"(x), "=f"(y) : "l"(d));
}
static __device__ __forceinline__ void fma2(unsigned long long &d,
                                            unsigned long long a,
                                            unsigned long long b){
    asm("fma.rn.f32x2 %0, %1, %2, %0;" : "+l"(d) : "l"(a), "l"(b));
}

// ---------------- kernel 1: row L2 norms (warp per 512-float row) ----------
__global__ void norms_kernel(const float* __restrict__ vcls,
                             const float* __restrict__ vp,
                             const float* __restrict__ text){
    int w    = (blockIdx.x * blockDim.x + threadIdx.x) >> 5;
    int lane = threadIdx.x & 31;
    const int NWARPS = BB*NN + CC + BB;   // 66112
    if (w >= NWARPS) return;
    const float* src; float* dst;
    if (w < BB*NN)            { src = vp   + (size_t)w * DD;               dst = g_rnp + w; }
    else if (w < BB*NN + CC)  { src = text + (size_t)(w - BB*NN) * DD;     dst = g_rnt + (w - BB*NN); }
    else                      { src = vcls + (size_t)(w - BB*NN - CC) * DD; dst = g_rnc + (w - BB*NN - CC); }
    float ss = 0.f;
    #pragma unroll
    for (int j = 0; j < 4; j++){
        float4 v = *reinterpret_cast<const float4*>(src + ((j*32 + lane) << 2));
        ss += v.x*v.x + v.y*v.y + v.z*v.z + v.w*v.w;
    }
    #pragma unroll
    for (int off = 16; off; off >>= 1) ss += __shfl_xor_sync(0xffffffffu, ss, off);
    if (lane == 0) *dst = 1.0f / fmaxf(sqrtf(ss), 1e-12f);
}

// ---------------- kernel 2: global affinity, writes 0.3*softmax ------------
__global__ __launch_bounds__(512) void affg_kernel(const float* __restrict__ vcls,
                                                   const float* __restrict__ text,
                                                   float* __restrict__ out){
    __shared__ float sv[DD];
    __shared__ float red[16];
    int b = blockIdx.x, tid = threadIdx.x;
    sv[tid] = vcls[b*DD + tid];
    __syncthreads();
    const float* t = text + (size_t)tid * DD;
    float dot = 0.f;
    #pragma unroll 4
    for (int k = 0; k < DD; k += 4){
        float4 v = *reinterpret_cast<const float4*>(t + k);
        dot += v.x*sv[k] + v.y*sv[k+1] + v.z*sv[k+2] + v.w*sv[k+3];
    }
    float logit = dot * g_rnc[b] * g_rnt[tid] * INV_TEMP;
    int lane = tid & 31, wid = tid >> 5;
    float m = logit;
    #pragma unroll
    for (int off = 16; off; off >>= 1) m = fmaxf(m, __shfl_xor_sync(0xffffffffu, m, off));
    if (lane == 0) red[wid] = m;
    __syncthreads();
    float bm = red[0];
    #pragma unroll
    for (int i = 1; i < 16; i++) bm = fmaxf(bm, red[i]);
    __syncthreads();
    float e = __expf(logit - bm);
    float s = e;
    #pragma unroll
    for (int off = 16; off; off >>= 1) s += __shfl_xor_sync(0xffffffffu, s, off);
    if (lane == 0) red[wid] = s;
    __syncthreads();
    float bs = 0.f;
    #pragma unroll
    for (int i = 0; i < 16; i++) bs += red[i];
    out[b*CC + tid] = 0.3f * e / bs;
}

// ---------------- kernel 3: main GEMM + fused softmax + transposed write ----
// block: (n-tile of 64 patches) x (all 512 classes), 512 threads
// thread: 8 m-rows (mg=tid/64) x 8 classes (ng=tid%64: c = ng*4 + jj*256 + t)
__global__ __launch_bounds__(512, 1) void gemm_softmax_kernel(const float* __restrict__ vp,
                                                              const float* __restrict__ text){
    __shared__ __align__(16) float As[16][68];    // padded: conflict-light stores
    __shared__ __align__(16) float Bs[16][516];   // padded: conflict-free f4 reads
    __shared__ float s_rnp[64];
    __shared__ float sred[2][64];

    const int b  = blockIdx.y;
    const int nx = blockIdx.x;
    const int tid  = threadIdx.x;
    const int mg   = tid >> 6;      // 0..7
    const int ng   = tid & 63;      // 0..63
    const int w2   = ng >> 5;       // which of the 2 warps sharing these m-rows
    const int lane = tid & 31;

    const float* A = vp + ((size_t)b * NN + (size_t)nx * 64) * DD;
    if (tid < 64) s_rnp[tid] = g_rnp[b*NN + nx*64 + tid];

    unsigned long long acc[8][4];
    #pragma unroll
    for (int i = 0; i < 8; i++)
        #pragma unroll
        for (int j = 0; j < 4; j++) acc[i][j] = 0ULL;

    const int arow = tid >> 3;        // 0..63
    const int akk  = (tid & 7) * 2;   // 0,2,..,14

    for (int kt = 0; kt < DD/16; ++kt){
        __syncthreads();
        {   // A tile: 64 rows x 16 k
            float2 v = *reinterpret_cast<const float2*>(A + (size_t)arow*DD + kt*16 + akk);
            As[akk  ][arow] = v.x;
            As[akk+1][arow] = v.y;
        }
        #pragma unroll
        for (int i = 0; i < 4; i++){  // B tile: 512 classes x 16 k
            int f  = tid + i*512;
            int c  = f >> 2;
            int k4 = (f & 3) << 2;
            float4 v = *reinterpret_cast<const float4*>(text + (size_t)c*DD + kt*16 + k4);
            Bs[k4  ][c] = v.x;
            Bs[k4+1][c] = v.y;
            Bs[k4+2][c] = v.z;
            Bs[k4+3][c] = v.w;
        }
        __syncthreads();
        #pragma unroll
        for (int kk = 0; kk < 16; kk++){
            float4 a0 = *reinterpret_cast<const float4*>(&As[kk][mg*8]);
            float4 a1 = *reinterpret_cast<const float4*>(&As[kk][mg*8 + 4]);
            float4 b0 = *reinterpret_cast<const float4*>(&Bs[kk][ng*4]);
            float4 b1 = *reinterpret_cast<const float4*>(&Bs[kk][ng*4 + 256]);
            unsigned long long bp0 = pk2(b0.x, b0.y), bp1 = pk2(b0.z, b0.w);
            unsigned long long bp2 = pk2(b1.x, b1.y), bp3 = pk2(b1.z, b1.w);
            float av[8] = {a0.x,a0.y,a0.z,a0.w,a1.x,a1.y,a1.z,a1.w};
            #pragma unroll
            for (int mm = 0; mm < 8; mm++){
                unsigned long long ap = pk2(av[mm], av[mm]);
                fma2(acc[mm][0], ap, bp0);
                fma2(acc[mm][1], ap, bp1);
                fma2(acc[mm][2], ap, bp2);
                fma2(acc[mm][3], ap, bp3);
            }
        }
    }

    // ---- epilogue: scale -> softmax over c (64 threads = 2 warps share rows)
    float4 rt0 = *reinterpret_cast<const float4*>(&g_rnt[ng*4]);
    float4 rt1 = *reinterpret_cast<const float4*>(&g_rnt[ng*4 + 256]);
    float rt[8] = {rt0.x,rt0.y,rt0.z,rt0.w,rt1.x,rt1.y,rt1.z,rt1.w};

    float f[8][8];
    float rmax[8];
    #pragma unroll
    for (int mm = 0; mm < 8; mm++){
        float rp = s_rnp[mg*8 + mm] * INV_TEMP;
        #pragma unroll
        for (int p = 0; p < 4; p++) upk2(acc[mm][p], f[mm][2*p], f[mm][2*p+1]);
        float mx = -3.0e38f;
        #pragma unroll
        for (int q = 0; q < 8; q++){
            float v = f[mm][q] * rp * rt[q];
            f[mm][q] = v;
            mx = fmaxf(mx, v);
        }
        #pragma unroll
        for (int off = 16; off; off >>= 1) mx = fmaxf(mx, __shfl_xor_sync(0xffffffffu, mx, off));
        rmax[mm] = mx;
    }
    if (lane == 0){
        #pragma unroll
        for (int mm = 0; mm < 8; mm++) sred[w2][mg*8 + mm] = rmax[mm];
    }
    __syncthreads();
    float gmax[8];
    #pragma unroll
    for (int mm = 0; mm < 8; mm++) gmax[mm] = fmaxf(sred[0][mg*8+mm], sred[1][mg*8+mm]);
    __syncthreads();
    float rsum[8];
    #pragma unroll
    for (int mm = 0; mm < 8; mm++){
        float s = 0.f;
        #pragma unroll
        for (int q = 0; q < 8; q++){
            float e = __expf(f[mm][q] - gmax[mm]);
            f[mm][q] = e;
            s += e;
        }
        #pragma unroll
        for (int off = 16; off; off >>= 1) s += __shfl_xor_sync(0xffffffffu, s, off);
        rsum[mm] = s;
    }
    if (lane == 0){
        #pragma unroll
        for (int mm = 0; mm < 8; mm++) sred[w2][mg*8 + mm] = rsum[mm];
    }
    __syncthreads();
    float inv[8];
    #pragma unroll
    for (int mm = 0; mm < 8; mm++) inv[mm] = 1.0f / (sred[0][mg*8+mm] + sred[1][mg*8+mm]);

    // ---- transposed write: g_aff[b][c][n], 8 contiguous n per (thread,c)
    float* dst = g_aff + (size_t)b * CC * NN + (size_t)nx * 64 + (size_t)mg * 8;
    #pragma unroll
    for (int q = 0; q < 8; q++){
        int c = ng*4 + (q >> 2)*256 + (q & 3);
        float4 o0 = make_float4(f[0][q]*inv[0], f[1][q]*inv[1], f[2][q]*inv[2], f[3][q]*inv[3]);
        float4 o1 = make_float4(f[4][q]*inv[4], f[5][q]*inv[5], f[6][q]*inv[6], f[7][q]*inv[7]);
        *reinterpret_cast<float4*>(dst + (size_t)c*NN)     = o0;
        *reinterpret_cast<float4*>(dst + (size_t)c*NN + 4) = o1;
    }
}

// ---------------- kernel 4: top-16 over N per (b,c), blend into out --------
__global__ void topk_kernel(float* __restrict__ out){
    int w    = (blockIdx.x * blockDim.x + threadIdx.x) >> 5;  // b*512 + c
    int lane = threadIdx.x & 31;
    if (w >= BB*CC) return;
    const float* p = g_aff + (size_t)w * NN;
    float v[32];
    #pragma unroll
    for (int j = 0; j < 32; j++) v[j] = p[j*32 + lane];
    float lm = -1e30f; int li = 0;
    #pragma unroll
    for (int j = 0; j < 32; j++) if (v[j] > lm){ lm = v[j]; li = j; }
    float sum = 0.f;
    for (int it = 0; it < KTOP; ++it){
        float m = lm; int src = lane;
        #pragma unroll
        for (int off = 16; off; off >>= 1){
            float om = __shfl_xor_sync(0xffffffffu, m,   off);
            int   os = __shfl_xor_sync(0xffffffffu, src, off);
            if (om > m || (om == m && os < src)){ m = om; src = os; }
        }
        sum += m;
        if (lane == src){
            #pragma unroll
            for (int j = 0; j < 32; j++) if (j == li) v[j] = -1e30f;
            lm = -1e30f; li = 0;
            #pragma unroll
            for (int j = 0; j < 32; j++) if (v[j] > lm){ lm = v[j]; li = j; }
        }
    }
    if (lane == 0) out[w] += 0.7f * (sum * (1.0f/(float)KTOP));
}

// ---------------- launch ----------------------------------------------------
extern "C" void kernel_launch(void* const* d_in, const int* in_sizes, int n_in,
                              void* d_out, int out_size){
    const float* vcls = nullptr;
    const float* vp   = nullptr;
    const float* text = nullptr;
    for (int i = 0; i < n_in; i++){
        if      (in_sizes[i] == BB*DD)            vcls = (const float*)d_in[i];
        else if (in_sizes[i] == BB*NN*DD)         vp   = (const float*)d_in[i];
        else if (in_sizes[i] == CC*DD)            text = (const float*)d_in[i];
    }
    float* out = (float*)d_out;

    const int nwarps = BB*NN + CC + BB;             // 66112
    norms_kernel<<<(nwarps + 7)/8, 256>>>(vcls, vp, text);
    affg_kernel<<<BB, 512>>>(vcls, text, out);
    gemm_softmax_kernel<<<dim3(NN/64, BB), 512>>>(vp, text);
    topk_kernel<<<(BB*CC + 7)/8, 256>>>(out);
}

// round 4
// speedup vs baseline: 1.2778x; 1.2760x over previous
#include <cuda_runtime.h>
#include <cuda_bf16.h>
#include <math.h>
#include <stdint.h>

#define BB 64
#define NN 1024
#define DD 512
#define CC 512
#define KTOP 16
#define INV_TEMP (1.0f/0.07f)

// ---------------- scratch (device globals: no allocations allowed) ----------
__device__ float g_aff[(size_t)BB * CC * NN];     // [b][c][n] unnormalized exp
__device__ float g_rz [BB * NN];                  // 1/rowsum per (b,n)
__device__ float g_rnp[BB * NN];                  // 1/||patch||
__device__ float g_rnt[CC];
__device__ float g_rnc[BB];
__device__ __nv_bfloat16 g_vph[(size_t)BB*NN*DD]; // patches hi
__device__ __nv_bfloat16 g_vpl[(size_t)BB*NN*DD]; // patches lo
__device__ __nv_bfloat16 g_txh[(size_t)CC*DD];    // text hi
__device__ __nv_bfloat16 g_txl[(size_t)CC*DD];    // text lo

// ================= helpers ====================================================
static __device__ __forceinline__ uint32_t smem_u32(const void* p){
    uint32_t a;
    asm("{ .reg .u64 t; cvta.to.shared.u64 t, %1; cvt.u32.u64 %0, t; }" : "=r"(a) : "l"(p));
    return a;
}
static __device__ __forceinline__ void cpasync16(uint32_t dst, const void* src){
    asm volatile("cp.async.cg.shared.global [%0], [%1], 16;" :: "r"(dst), "l"(src) : "memory");
}
static __device__ __forceinline__ uint32_t swz(uint32_t o){ return o ^ ((o >> 3) & 0x70u); }

static __device__ __forceinline__ void ldsm4(uint32_t &r0, uint32_t &r1,
                                             uint32_t &r2, uint32_t &r3, uint32_t addr){
    asm volatile("ldmatrix.sync.aligned.m8n8.x4.shared.b16 {%0,%1,%2,%3}, [%4];"
        : "=r"(r0), "=r"(r1), "=r"(r2), "=r"(r3) : "r"(addr));
}
static __device__ __forceinline__ void mma16816(float* d, const uint32_t* a,
                                                uint32_t b0, uint32_t b1){
    asm volatile("mma.sync.aligned.m16n8k16.row.col.f32.bf16.bf16.f32 "
        "{%0,%1,%2,%3}, {%4,%5,%6,%7}, {%8,%9}, {%0,%1,%2,%3};"
        : "+f"(d[0]), "+f"(d[1]), "+f"(d[2]), "+f"(d[3])
        : "r"(a[0]), "r"(a[1]), "r"(a[2]), "r"(a[3]), "r"(b0), "r"(b1));
}

// ================= kernel 1: convert to bf16 hi/lo + L2 norms ================
__global__ void convert_kernel(const float* __restrict__ vcls,
                               const float* __restrict__ vp,
                               const float* __restrict__ text){
    int w    = (blockIdx.x * blockDim.x + threadIdx.x) >> 5;
    int lane = threadIdx.x & 31;
    const int NW = BB*NN + CC + BB;
    if (w >= NW) return;
    const float* src; __nv_bfloat16* hi = nullptr; __nv_bfloat16* lo = nullptr; float* rdst;
    if (w < BB*NN){ src = vp + (size_t)w*DD; hi = g_vph + (size_t)w*DD; lo = g_vpl + (size_t)w*DD; rdst = g_rnp + w; }
    else if (w < BB*NN + CC){ int t = w - BB*NN; src = text + (size_t)t*DD; hi = g_txh + (size_t)t*DD; lo = g_txl + (size_t)t*DD; rdst = g_rnt + t; }
    else { int ci = w - BB*NN - CC; src = vcls + (size_t)ci*DD; rdst = g_rnc + ci; }
    float ss = 0.f;
    #pragma unroll
    for (int j = 0; j < 4; j++){
        int o = (j*32 + lane) * 4;
        float4 v = *reinterpret_cast<const float4*>(src + o);
        ss += v.x*v.x + v.y*v.y + v.z*v.z + v.w*v.w;
        if (hi){
            __nv_bfloat162 h01 = __floats2bfloat162_rn(v.x, v.y);
            __nv_bfloat162 h23 = __floats2bfloat162_rn(v.z, v.w);
            float rx = v.x - __bfloat162float(h01.x);
            float ry = v.y - __bfloat162float(h01.y);
            float rz2= v.z - __bfloat162float(h23.x);
            float rw = v.w - __bfloat162float(h23.y);
            __nv_bfloat162 l01 = __floats2bfloat162_rn(rx, ry);
            __nv_bfloat162 l23 = __floats2bfloat162_rn(rz2, rw);
            union { __nv_bfloat162 h2[2]; uint2 u; } PH, PL;
            PH.h2[0]=h01; PH.h2[1]=h23; PL.h2[0]=l01; PL.h2[1]=l23;
            *reinterpret_cast<uint2*>(hi + o) = PH.u;
            *reinterpret_cast<uint2*>(lo + o) = PL.u;
        }
    }
    #pragma unroll
    for (int off = 16; off; off >>= 1) ss += __shfl_xor_sync(0xffffffffu, ss, off);
    if (lane == 0) *rdst = 1.0f / fmaxf(sqrtf(ss), 1e-12f);
}

// ================= kernel 2: global affinity, writes 0.3*softmax ============
__global__ __launch_bounds__(512) void affg_kernel(const float* __restrict__ vcls,
                                                   const float* __restrict__ text,
                                                   float* __restrict__ out){
    __shared__ float sv[DD];
    __shared__ float red[16];
    int b = blockIdx.x, tid = threadIdx.x;
    sv[tid] = vcls[b*DD + tid];
    __syncthreads();
    const float* t = text + (size_t)tid * DD;
    float dot = 0.f;
    #pragma unroll 4
    for (int k = 0; k < DD; k += 4){
        float4 v = *reinterpret_cast<const float4*>(t + k);
        dot += v.x*sv[k] + v.y*sv[k+1] + v.z*sv[k+2] + v.w*sv[k+3];
    }
    float logit = dot * g_rnc[b] * g_rnt[tid] * INV_TEMP;
    int lane = tid & 31, wid = tid >> 5;
    float m = logit;
    #pragma unroll
    for (int off = 16; off; off >>= 1) m = fmaxf(m, __shfl_xor_sync(0xffffffffu, m, off));
    if (lane == 0) red[wid] = m;
    __syncthreads();
    float bm = red[0];
    #pragma unroll
    for (int i = 1; i < 16; i++) bm = fmaxf(bm, red[i]);
    __syncthreads();
    float e = __expf(logit - bm);
    float s = e;
    #pragma unroll
    for (int off = 16; off; off >>= 1) s += __shfl_xor_sync(0xffffffffu, s, off);
    if (lane == 0) red[wid] = s;
    __syncthreads();
    float bs = 0.f;
    #pragma unroll
    for (int i = 0; i < 16; i++) bs += red[i];
    out[b*CC + tid] = 0.3f * e / bs;
}

// ================= kernel 3: HMMA GEMM (bf16x3) + fused softmax ==============
// CTA: 64 patches x 512 classes, 512 threads (16 warps: mw=wid>>3 in {0,1},
// nw=wid&7). Warp tile 32 rows x 64 cols. K_eff = 3*512 (hh, lh, hl).
#define SM_A0   0u
#define SM_A1   8192u
#define SM_B0   16384u
#define SM_B1   81920u
#define SM_AUX  147456u
#define SM_DYN  (152064u + 1024u)

static __device__ __forceinline__ void issue_loads(int it, uint32_t a_dst, uint32_t b_dst,
                                                   int pb, int tid){
    int s = it >> 3, kt = it & 7;
    const __nv_bfloat16* Asrc = (s == 1) ? g_vpl : g_vph;
    const __nv_bfloat16* Bsrc = (s == 2) ? g_txl : g_txh;
    const __nv_bfloat16* Ab = Asrc + ((size_t)pb * 64) * DD + kt * 64;
    const __nv_bfloat16* Bb = Bsrc + kt * 64;
    {   // A: 64 rows x 128B = 512 16B-chunks, one per thread
        int row = tid >> 3, c16 = tid & 7;
        cpasync16(a_dst + swz(row*128 + c16*16), Ab + (size_t)row*DD + c16*8);
    }
    #pragma unroll
    for (int t = 0; t < 8; t++){  // B: 512 rows x 128B = 4096 chunks
        int g = tid + t*512; int row = g >> 3; int c16 = g & 7;
        cpasync16(b_dst + swz(row*128 + c16*16), Bb + (size_t)row*DD + c16*8);
    }
    asm volatile("cp.async.commit_group;" ::: "memory");
}

__global__ __launch_bounds__(512, 1) void gemm_softmax_kernel(){
    extern __shared__ __align__(16) char dsm[];
    const uint32_t raw  = smem_u32(dsm);
    const uint32_t base = (raw + 1023u) & ~1023u;
    char* bp = dsm + (base - raw);

    const int tid = threadIdx.x;
    const int pb  = blockIdx.x;          // 0..1023
    const int b   = pb >> 4;
    const int nt  = pb & 15;

    const uint32_t ab[2]   = { base + SM_A0, base + SM_A1 };
    const uint32_t bbuf[2] = { base + SM_B0, base + SM_B1 };
    float* s_t    = reinterpret_cast<float*>(bp);                    // 512*68 f (overlays A/B)
    float* s_rnt  = reinterpret_cast<float*>(bp + SM_AUX);           // 512 f
    float* s_rnp  = reinterpret_cast<float*>(bp + SM_AUX + 2048);    // 64 f
    float* s_red  = reinterpret_cast<float*>(bp + SM_AUX + 2304);    // 64*8 f
    float* s_gmax = reinterpret_cast<float*>(bp + SM_AUX + 4352);    // 64 f

    const int wid  = tid >> 5;
    const int lane = tid & 31;
    const int mw   = wid >> 3;           // 0..1
    const int nw   = wid & 7;            // 0..7
    const int gid  = lane >> 2;          // row group 0..7
    const int tig  = lane & 3;

    #pragma unroll
    for (int i = tid; i < 512; i += 512) s_rnt[i] = g_rnt[i];
    if (tid < 64) s_rnp[tid] = g_rnp[pb*64 + tid];

    issue_loads(0, ab[0], bbuf[0], pb, tid);
    issue_loads(1, ab[1], bbuf[1], pb, tid);

    // ldmatrix lane addressing (canonical x4 fragment order)
    const int lr = (lane & 7) + ((lane >> 3) & 1) * 8;   // row within 16
    const int lk = (lane >> 4) * 16;                     // 16B col half

    float acc[2][8][4];
    #pragma unroll
    for (int mi = 0; mi < 2; mi++)
        #pragma unroll
        for (int j = 0; j < 8; j++)
            #pragma unroll
            for (int v = 0; v < 4; v++) acc[mi][j][v] = 0.f;

    for (int it = 0; it < 24; ++it){
        const int cur = it & 1;
        if (it == 23) asm volatile("cp.async.wait_group 0;" ::: "memory");
        else          asm volatile("cp.async.wait_group 1;" ::: "memory");
        __syncthreads();

        const uint32_t abase = ab[cur];
        const uint32_t bbase = bbuf[cur];
        #pragma unroll
        for (int ks = 0; ks < 4; ks++){
            uint32_t af[2][4];
            #pragma unroll
            for (int mi = 0; mi < 2; mi++){
                int r = mw*32 + mi*16 + lr;
                ldsm4(af[mi][0], af[mi][1], af[mi][2], af[mi][3],
                      abase + swz((uint32_t)(r*128 + ks*32 + lk)));
            }
            uint32_t bf[4][4];
            #pragma unroll
            for (int jj = 0; jj < 4; jj++){
                int r = nw*64 + jj*16 + lr;
                ldsm4(bf[jj][0], bf[jj][1], bf[jj][2], bf[jj][3],
                      bbase + swz((uint32_t)(r*128 + ks*32 + lk)));
            }
            #pragma unroll
            for (int mi = 0; mi < 2; mi++)
                #pragma unroll
                for (int j = 0; j < 8; j++)
                    mma16816(acc[mi][j], af[mi], bf[j>>1][j&1], bf[j>>1][(j&1)+2]);
        }
        __syncthreads();
        if (it + 2 < 24) issue_loads(it + 2, ab[cur], bbuf[cur], pb, tid);
    }

    // ---- epilogue: scale, softmax over full 512 cols, transposed exp store
    float rs[2][2], rt[8][2];
    #pragma unroll
    for (int mi = 0; mi < 2; mi++)
        #pragma unroll
        for (int h = 0; h < 2; h++)
            rs[mi][h] = s_rnp[mw*32 + mi*16 + h*8 + gid] * INV_TEMP;
    #pragma unroll
    for (int j = 0; j < 8; j++){
        int c0 = nw*64 + j*8 + tig*2;
        rt[j][0] = s_rnt[c0]; rt[j][1] = s_rnt[c0+1];
    }
    #pragma unroll
    for (int mi = 0; mi < 2; mi++)
        #pragma unroll
        for (int j = 0; j < 8; j++)
            #pragma unroll
            for (int v = 0; v < 4; v++)
                acc[mi][j][v] *= rs[mi][v>>1] * rt[j][v&1];

    // per-row max (warp slice), quad shuffle, 8-warp smem reduce
    #pragma unroll
    for (int mi = 0; mi < 2; mi++)
        #pragma unroll
        for (int h = 0; h < 2; h++){
            float mx = -3.0e38f;
            #pragma unroll
            for (int j = 0; j < 8; j++)
                mx = fmaxf(mx, fmaxf(acc[mi][j][2*h], acc[mi][j][2*h+1]));
            mx = fmaxf(mx, __shfl_xor_sync(0xffffffffu, mx, 1));
            mx = fmaxf(mx, __shfl_xor_sync(0xffffffffu, mx, 2));
            if (tig == 0) s_red[(mw*32 + mi*16 + h*8 + gid)*8 + nw] = mx;
        }
    __syncthreads();
    if (tid < 64){
        float m = s_red[tid*8];
        #pragma unroll
        for (int k = 1; k < 8; k++) m = fmaxf(m, s_red[tid*8 + k]);
        s_gmax[tid] = m;
    }
    __syncthreads();

    // exp + row sum
    #pragma unroll
    for (int mi = 0; mi < 2; mi++)
        #pragma unroll
        for (int h = 0; h < 2; h++){
            float gm = s_gmax[mw*32 + mi*16 + h*8 + gid];
            float sm = 0.f;
            #pragma unroll
            for (int j = 0; j < 8; j++){
                float e0 = __expf(acc[mi][j][2*h]   - gm);
                float e1 = __expf(acc[mi][j][2*h+1] - gm);
                acc[mi][j][2*h] = e0; acc[mi][j][2*h+1] = e1;
                sm += e0 + e1;
            }
            sm += __shfl_xor_sync(0xffffffffu, sm, 1);
            sm += __shfl_xor_sync(0xffffffffu, sm, 2);
            if (tig == 0) s_red[(mw*32 + mi*16 + h*8 + gid)*8 + nw] = sm;
        }

    // transposed store of exp into padded smem [c][n], stride 68 (conflict-free)
    #pragma unroll
    for (int mi = 0; mi < 2; mi++)
        #pragma unroll
        for (int j = 0; j < 8; j++)
            #pragma unroll
            for (int v = 0; v < 4; v++){
                int col = nw*64 + j*8 + tig*2 + (v&1);
                int row = mw*32 + mi*16 + (v>>1)*8 + gid;
                s_t[col*68 + row] = acc[mi][j][v];
            }
    __syncthreads();
    if (tid < 64){
        float s = 0.f;
        #pragma unroll
        for (int k = 0; k < 8; k++) s += s_red[tid*8 + k];
        g_rz[b*NN + nt*64 + tid] = 1.0f / s;
    }

    // coalesced copy-out: g_aff[b][c][nt*64 + n]
    const size_t obase = (size_t)b * CC * NN + (size_t)nt * 64;
    const int cpart = tid >> 6;
    const int n     = tid & 63;
    #pragma unroll 4
    for (int itc = 0; itc < 64; itc++){
        int c = itc*8 + cpart;
        g_aff[obase + (size_t)c * NN + n] = s_t[c*68 + n];
    }
}

// ================= kernel 4: top-16 over N per (b,c), blend ==================
__global__ void topk_kernel(float* __restrict__ out){
    int w    = (blockIdx.x * blockDim.x + threadIdx.x) >> 5;  // b*512 + c
    int lane = threadIdx.x & 31;
    if (w >= BB*CC) return;
    int b = w >> 9;
    const float4* p  = reinterpret_cast<const float4*>(g_aff + (size_t)w * NN);
    const float4* rz = reinterpret_cast<const float4*>(g_rz  + (size_t)b * NN);

    unsigned v[32], cm[8];
    #pragma unroll
    for (int j = 0; j < 8; j++){
        float4 e = p[j*32 + lane];
        float4 z = rz[j*32 + lane];
        v[4*j+0] = __float_as_uint(e.x*z.x);
        v[4*j+1] = __float_as_uint(e.y*z.y);
        v[4*j+2] = __float_as_uint(e.z*z.z);
        v[4*j+3] = __float_as_uint(e.w*z.w);
        unsigned a = v[4*j] > v[4*j+1] ? v[4*j] : v[4*j+1];
        unsigned c2 = v[4*j+2] > v[4*j+3] ? v[4*j+2] : v[4*j+3];
        cm[j] = a > c2 ? a : c2;
    }
    unsigned lm = 0; int lc = 0;
    #pragma unroll
    for (int j = 0; j < 8; j++) if (cm[j] > lm){ lm = cm[j]; lc = j; }

    float sum = 0.f;
    #pragma unroll
    for (int it = 0; it < KTOP; ++it){
        unsigned m;
        asm("redux.sync.max.u32 %0, %1, 0xffffffff;" : "=r"(m) : "r"(lm));
        sum += __uint_as_float(m);
        unsigned msk = __ballot_sync(0xffffffffu, lm == m);
        if (lane == __ffs(msk) - 1){
            #pragma unroll
            for (int j = 0; j < 8; j++) if (j == lc){
                bool done = false;
                #pragma unroll
                for (int q = 0; q < 4; q++){
                    if (!done && v[4*j+q] == m){ v[4*j+q] = 0u; done = true; }
                }
                unsigned a = v[4*j] > v[4*j+1] ? v[4*j] : v[4*j+1];
                unsigned c2 = v[4*j+2] > v[4*j+3] ? v[4*j+2] : v[4*j+3];
                cm[j] = a > c2 ? a : c2;
            }
            lm = 0; lc = 0;
            #pragma unroll
            for (int j = 0; j < 8; j++) if (cm[j] > lm){ lm = cm[j]; lc = j; }
        }
    }
    if (lane == 0) out[w] += 0.7f * (sum * (1.0f / (float)KTOP));
}

// ================= launch =====================================================
extern "C" void kernel_launch(void* const* d_in, const int* in_sizes, int n_in,
                              void* d_out, int out_size){
    const float* vcls = nullptr;
    const float* vp   = nullptr;
    const float* text = nullptr;
    for (int i = 0; i < n_in; i++){
        if      (in_sizes[i] == BB*DD)     vcls = (const float*)d_in[i];
        else if (in_sizes[i] == BB*NN*DD)  vp   = (const float*)d_in[i];
        else if (in_sizes[i] == CC*DD)     text = (const float*)d_in[i];
    }
    float* out = (float*)d_out;

    cudaFuncSetAttribute(gemm_softmax_kernel,
                         cudaFuncAttributeMaxDynamicSharedMemorySize, SM_DYN);

    const int nwarps = BB*NN + CC + BB;
    convert_kernel<<<(nwarps*32 + 255)/256, 256>>>(vcls, vp, text);
    affg_kernel<<<BB, 512>>>(vcls, text, out);
    gemm_softmax_kernel<<<1024, 512, SM_DYN>>>();
    topk_kernel<<<(BB*CC*32 + 255)/256, 256>>>(out);
}

// round 5
// speedup vs baseline: 3.6142x; 2.8284x over previous
#include <cuda_runtime.h>
#include <cuda_fp16.h>
#include <math.h>
#include <stdint.h>

#define BB 64
#define NN 1024
#define DD 512
#define CC 512
#define KTOP 16
#define INV_TEMP (1.0f/0.07f)

// ---------------- scratch (device globals: no allocations allowed) ----------
__device__ float g_aff[(size_t)BB * CC * NN];     // [b][c][n] normalized softmax p
__device__ float g_rnp[BB * NN];                  // 1/||patch||
__device__ float g_rnt[CC];
__device__ float g_rnc[BB];
__device__ __half g_vph[(size_t)BB*NN*DD];        // patches fp16
__device__ __half g_txh[(size_t)CC*DD];           // text fp16

// ================= helpers ====================================================
static __device__ __forceinline__ uint32_t smem_u32(const void* p){
    uint32_t a;
    asm("{ .reg .u64 t; cvta.to.shared.u64 t, %1; cvt.u32.u64 %0, t; }" : "=r"(a) : "l"(p));
    return a;
}
static __device__ __forceinline__ void cpasync16(uint32_t dst, const void* src){
    asm volatile("cp.async.cg.shared.global [%0], [%1], 16;" :: "r"(dst), "l"(src) : "memory");
}
static __device__ __forceinline__ uint32_t swz(uint32_t o){ return o ^ ((o >> 3) & 0x70u); }

static __device__ __forceinline__ void ldsm4(uint32_t &r0, uint32_t &r1,
                                             uint32_t &r2, uint32_t &r3, uint32_t addr){
    asm volatile("ldmatrix.sync.aligned.m8n8.x4.shared.b16 {%0,%1,%2,%3}, [%4];"
        : "=r"(r0), "=r"(r1), "=r"(r2), "=r"(r3) : "r"(addr));
}
static __device__ __forceinline__ void mma16816(float* d, const uint32_t* a,
                                                uint32_t b0, uint32_t b1){
    asm volatile("mma.sync.aligned.m16n8k16.row.col.f32.f16.f16.f32 "
        "{%0,%1,%2,%3}, {%4,%5,%6,%7}, {%8,%9}, {%0,%1,%2,%3};"
        : "+f"(d[0]), "+f"(d[1]), "+f"(d[2]), "+f"(d[3])
        : "r"(a[0]), "r"(a[1]), "r"(a[2]), "r"(a[3]), "r"(b0), "r"(b1));
}

// ================= kernel 1: convert to fp16 + L2 norms ======================
__global__ void convert_kernel(const float* __restrict__ vcls,
                               const float* __restrict__ vp,
                               const float* __restrict__ text){
    int w    = (blockIdx.x * blockDim.x + threadIdx.x) >> 5;
    int lane = threadIdx.x & 31;
    const int NW = BB*NN + CC + BB;
    if (w >= NW) return;
    const float* src; __half* hi = nullptr; float* rdst;
    if (w < BB*NN){ src = vp + (size_t)w*DD; hi = g_vph + (size_t)w*DD; rdst = g_rnp + w; }
    else if (w < BB*NN + CC){ int t = w - BB*NN; src = text + (size_t)t*DD; hi = g_txh + (size_t)t*DD; rdst = g_rnt + t; }
    else { int ci = w - BB*NN - CC; src = vcls + (size_t)ci*DD; rdst = g_rnc + ci; }
    float ss = 0.f;
    #pragma unroll
    for (int j = 0; j < 4; j++){
        int o = (j*32 + lane) * 4;
        float4 v = *reinterpret_cast<const float4*>(src + o);
        ss += v.x*v.x + v.y*v.y + v.z*v.z + v.w*v.w;
        if (hi){
            union { __half2 h2[2]; uint2 u; } P;
            P.h2[0] = __floats2half2_rn(v.x, v.y);
            P.h2[1] = __floats2half2_rn(v.z, v.w);
            *reinterpret_cast<uint2*>(hi + o) = P.u;
        }
    }
    #pragma unroll
    for (int off = 16; off; off >>= 1) ss += __shfl_xor_sync(0xffffffffu, ss, off);
    if (lane == 0) *rdst = 1.0f / fmaxf(sqrtf(ss), 1e-12f);
}

// ================= kernel 2: global affinity, writes 0.3*softmax ============
__global__ __launch_bounds__(512) void affg_kernel(const float* __restrict__ vcls,
                                                   const float* __restrict__ text,
                                                   float* __restrict__ out){
    __shared__ float sv[DD];
    __shared__ float red[16];
    int b = blockIdx.x, tid = threadIdx.x;
    sv[tid] = vcls[b*DD + tid];
    __syncthreads();
    const float* t = text + (size_t)tid * DD;
    float dot = 0.f;
    #pragma unroll 4
    for (int k = 0; k < DD; k += 4){
        float4 v = *reinterpret_cast<const float4*>(t + k);
        dot += v.x*sv[k] + v.y*sv[k+1] + v.z*sv[k+2] + v.w*sv[k+3];
    }
    float logit = dot * g_rnc[b] * g_rnt[tid] * INV_TEMP;
    int lane = tid & 31, wid = tid >> 5;
    float m = logit;
    #pragma unroll
    for (int off = 16; off; off >>= 1) m = fmaxf(m, __shfl_xor_sync(0xffffffffu, m, off));
    if (lane == 0) red[wid] = m;
    __syncthreads();
    float bm = red[0];
    #pragma unroll
    for (int i = 1; i < 16; i++) bm = fmaxf(bm, red[i]);
    __syncthreads();
    float e = __expf(logit - bm);
    float s = e;
    #pragma unroll
    for (int off = 16; off; off >>= 1) s += __shfl_xor_sync(0xffffffffu, s, off);
    if (lane == 0) red[wid] = s;
    __syncthreads();
    float bs = 0.f;
    #pragma unroll
    for (int i = 0; i < 16; i++) bs += red[i];
    out[b*CC + tid] = 0.3f * e / bs;
}

// ================= kernel 3: fp16 HMMA GEMM + fused softmax ==================
// CTA: 64 patches x 512 classes, 512 threads (16 warps: mw=wid>>3, nw=wid&7).
// Warp tile 32 rows x 64 cols. K = 512 (8 iters of kc=64), fp16 single pass.
#define SM_A0   0u
#define SM_A1   8192u
#define SM_B0   16384u
#define SM_B1   81920u
#define SM_AUX  147456u
#define SM_DYN  (152576u + 1024u)

static __device__ __forceinline__ void issue_loads(int kt, uint32_t a_dst, uint32_t b_dst,
                                                   int pb, int tid){
    const __half* Ab = g_vph + ((size_t)pb * 64) * DD + kt * 64;
    const __half* Bb = g_txh + kt * 64;
    {   // A: 64 rows x 128B = 512 16B-chunks, one per thread
        int row = tid >> 3, c16 = tid & 7;
        cpasync16(a_dst + swz(row*128 + c16*16), Ab + (size_t)row*DD + c16*8);
    }
    #pragma unroll
    for (int t = 0; t < 8; t++){  // B: 512 rows x 128B = 4096 chunks
        int g = tid + t*512; int row = g >> 3; int c16 = g & 7;
        cpasync16(b_dst + swz(row*128 + c16*16), Bb + (size_t)row*DD + c16*8);
    }
    asm volatile("cp.async.commit_group;" ::: "memory");
}

__global__ __launch_bounds__(512, 1) void gemm_softmax_kernel(){
    extern __shared__ __align__(16) char dsm[];
    const uint32_t raw  = smem_u32(dsm);
    const uint32_t base = (raw + 1023u) & ~1023u;
    char* bp = dsm + (base - raw);

    const int tid = threadIdx.x;
    const int pb  = blockIdx.x;          // 0..1023
    const int b   = pb >> 4;
    const int nt  = pb & 15;

    const uint32_t ab[2]   = { base + SM_A0, base + SM_A1 };
    const uint32_t bbuf[2] = { base + SM_B0, base + SM_B1 };
    float* s_t    = reinterpret_cast<float*>(bp);                    // 512*68 f (overlays A/B)
    float* s_rnt  = reinterpret_cast<float*>(bp + SM_AUX);           // 512 f
    float* s_rnp  = reinterpret_cast<float*>(bp + SM_AUX + 2048);    // 64 f
    float* s_red  = reinterpret_cast<float*>(bp + SM_AUX + 2304);    // 64*8 f
    float* s_gmax = reinterpret_cast<float*>(bp + SM_AUX + 4352);    // 64 f
    float* s_rzv  = reinterpret_cast<float*>(bp + SM_AUX + 4608);    // 64 f

    const int wid  = tid >> 5;
    const int lane = tid & 31;
    const int mw   = wid >> 3;           // 0..1
    const int nw   = wid & 7;            // 0..7
    const int gid  = lane >> 2;          // row group 0..7
    const int tig  = lane & 3;

    if (tid < 512) s_rnt[tid] = g_rnt[tid];
    if (tid < 64)  s_rnp[tid] = g_rnp[pb*64 + tid];

    issue_loads(0, ab[0], bbuf[0], pb, tid);
    issue_loads(1, ab[1], bbuf[1], pb, tid);

    // ldmatrix lane addressing (canonical x4 fragment order)
    const int lr = (lane & 7) + ((lane >> 3) & 1) * 8;   // row within 16
    const int lk = (lane >> 4) * 16;                     // 16B col half

    float acc[2][8][4];
    #pragma unroll
    for (int mi = 0; mi < 2; mi++)
        #pragma unroll
        for (int j = 0; j < 8; j++)
            #pragma unroll
            for (int v = 0; v < 4; v++) acc[mi][j][v] = 0.f;

    for (int it = 0; it < 8; ++it){
        const int cur = it & 1;
        if (it == 7) asm volatile("cp.async.wait_group 0;" ::: "memory");
        else         asm volatile("cp.async.wait_group 1;" ::: "memory");
        __syncthreads();

        const uint32_t abase = ab[cur];
        const uint32_t bbase = bbuf[cur];
        #pragma unroll
        for (int ks = 0; ks < 4; ks++){
            uint32_t af[2][4];
            #pragma unroll
            for (int mi = 0; mi < 2; mi++){
                int r = mw*32 + mi*16 + lr;
                ldsm4(af[mi][0], af[mi][1], af[mi][2], af[mi][3],
                      abase + swz((uint32_t)(r*128 + ks*32 + lk)));
            }
            uint32_t bf[4][4];
            #pragma unroll
            for (int jj = 0; jj < 4; jj++){
                int r = nw*64 + jj*16 + lr;
                ldsm4(bf[jj][0], bf[jj][1], bf[jj][2], bf[jj][3],
                      bbase + swz((uint32_t)(r*128 + ks*32 + lk)));
            }
            #pragma unroll
            for (int mi = 0; mi < 2; mi++)
                #pragma unroll
                for (int j = 0; j < 8; j++)
                    mma16816(acc[mi][j], af[mi], bf[j>>1][j&1], bf[j>>1][(j&1)+2]);
        }
        __syncthreads();
        if (it + 2 < 8) issue_loads(it + 2, ab[cur], bbuf[cur], pb, tid);
    }

    // ---- epilogue: scale, softmax over full 512 cols, normalized transposed store
    float rs[2][2], rt[8][2];
    #pragma unroll
    for (int mi = 0; mi < 2; mi++)
        #pragma unroll
        for (int h = 0; h < 2; h++)
            rs[mi][h] = s_rnp[mw*32 + mi*16 + h*8 + gid] * INV_TEMP;
    #pragma unroll
    for (int j = 0; j < 8; j++){
        int c0 = nw*64 + j*8 + tig*2;
        rt[j][0] = s_rnt[c0]; rt[j][1] = s_rnt[c0+1];
    }
    #pragma unroll
    for (int mi = 0; mi < 2; mi++)
        #pragma unroll
        for (int j = 0; j < 8; j++)
            #pragma unroll
            for (int v = 0; v < 4; v++)
                acc[mi][j][v] *= rs[mi][v>>1] * rt[j][v&1];

    // per-row max (warp slice), quad shuffle, 8-warp smem reduce
    #pragma unroll
    for (int mi = 0; mi < 2; mi++)
        #pragma unroll
        for (int h = 0; h < 2; h++){
            float mx = -3.0e38f;
            #pragma unroll
            for (int j = 0; j < 8; j++)
                mx = fmaxf(mx, fmaxf(acc[mi][j][2*h], acc[mi][j][2*h+1]));
            mx = fmaxf(mx, __shfl_xor_sync(0xffffffffu, mx, 1));
            mx = fmaxf(mx, __shfl_xor_sync(0xffffffffu, mx, 2));
            if (tig == 0) s_red[(mw*32 + mi*16 + h*8 + gid)*8 + nw] = mx;
        }
    __syncthreads();
    if (tid < 64){
        float m = s_red[tid*8];
        #pragma unroll
        for (int k = 1; k < 8; k++) m = fmaxf(m, s_red[tid*8 + k]);
        s_gmax[tid] = m;
    }
    __syncthreads();

    // exp + row sum
    #pragma unroll
    for (int mi = 0; mi < 2; mi++)
        #pragma unroll
        for (int h = 0; h < 2; h++){
            float gm = s_gmax[mw*32 + mi*16 + h*8 + gid];
            float sm = 0.f;
            #pragma unroll
            for (int j = 0; j < 8; j++){
                float e0 = __expf(acc[mi][j][2*h]   - gm);
                float e1 = __expf(acc[mi][j][2*h+1] - gm);
                acc[mi][j][2*h] = e0; acc[mi][j][2*h+1] = e1;
                sm += e0 + e1;
            }
            sm += __shfl_xor_sync(0xffffffffu, sm, 1);
            sm += __shfl_xor_sync(0xffffffffu, sm, 2);
            if (tig == 0) s_red[(mw*32 + mi*16 + h*8 + gid)*8 + nw] = sm;
        }
    __syncthreads();
    if (tid < 64){
        float s = 0.f;
        #pragma unroll
        for (int k = 0; k < 8; k++) s += s_red[tid*8 + k];
        s_rzv[tid] = 1.0f / s;
    }
    __syncthreads();

    // normalized transposed store into padded smem [c][n], stride 68
    #pragma unroll
    for (int mi = 0; mi < 2; mi++)
        #pragma unroll
        for (int j = 0; j < 8; j++)
            #pragma unroll
            for (int v = 0; v < 4; v++){
                int col = nw*64 + j*8 + tig*2 + (v&1);
                int row = mw*32 + mi*16 + (v>>1)*8 + gid;
                s_t[col*68 + row] = acc[mi][j][v] * s_rzv[row];
            }
    __syncthreads();

    // coalesced copy-out: g_aff[b][c][nt*64 + n]
    const size_t obase = (size_t)b * CC * NN + (size_t)nt * 64;
    const int cpart = tid >> 6;
    const int n     = tid & 63;
    #pragma unroll 4
    for (int itc = 0; itc < 64; itc++){
        int c = itc*8 + cpart;
        g_aff[obase + (size_t)c * NN + n] = s_t[c*68 + n];
    }
}

// ================= kernel 4: top-16 over N per (b,c), blend ==================
__global__ void topk_kernel(float* __restrict__ out){
    int w    = (blockIdx.x * blockDim.x + threadIdx.x) >> 5;  // b*512 + c
    int lane = threadIdx.x & 31;
    if (w >= BB*CC) return;
    const float4* p = reinterpret_cast<const float4*>(g_aff + (size_t)w * NN);

    unsigned v[32], cm[8];
    #pragma unroll
    for (int j = 0; j < 8; j++){
        float4 e = p[j*32 + lane];
        v[4*j+0] = __float_as_uint(e.x);
        v[4*j+1] = __float_as_uint(e.y);
        v[4*j+2] = __float_as_uint(e.z);
        v[4*j+3] = __float_as_uint(e.w);
        unsigned a = v[4*j] > v[4*j+1] ? v[4*j] : v[4*j+1];
        unsigned c2 = v[4*j+2] > v[4*j+3] ? v[4*j+2] : v[4*j+3];
        cm[j] = a > c2 ? a : c2;
    }
    unsigned lm = 0; int lc = 0;
    #pragma unroll
    for (int j = 0; j < 8; j++) if (cm[j] > lm){ lm = cm[j]; lc = j; }

    float sum = 0.f;
    #pragma unroll
    for (int it = 0; it < KTOP; ++it){
        unsigned m;
        asm("redux.sync.max.u32 %0, %1, 0xffffffff;" : "=r"(m) : "r"(lm));
        sum += __uint_as_float(m);
        unsigned msk = __ballot_sync(0xffffffffu, lm == m);
        if (lane == __ffs(msk) - 1){
            #pragma unroll
            for (int j = 0; j < 8; j++) if (j == lc){
                bool done = false;
                #pragma unroll
                for (int q = 0; q < 4; q++){
                    if (!done && v[4*j+q] == m){ v[4*j+q] = 0u; done = true; }
                }
                unsigned a = v[4*j] > v[4*j+1] ? v[4*j] : v[4*j+1];
                unsigned c2 = v[4*j+2] > v[4*j+3] ? v[4*j+2] : v[4*j+3];
                cm[j] = a > c2 ? a : c2;
            }
            lm = 0; lc = 0;
            #pragma unroll
            for (int j = 0; j < 8; j++) if (cm[j] > lm){ lm = cm[j]; lc = j; }
        }
    }
    if (lane == 0) out[w] += 0.7f * (sum * (1.0f / (float)KTOP));
}

// ================= launch =====================================================
extern "C" void kernel_launch(void* const* d_in, const int* in_sizes, int n_in,
                              void* d_out, int out_size){
    const float* vcls = nullptr;
    const float* vp   = nullptr;
    const float* text = nullptr;
    for (int i = 0; i < n_in; i++){
        if      (in_sizes[i] == BB*DD)     vcls = (const float*)d_in[i];
        else if (in_sizes[i] == BB*NN*DD)  vp   = (const float*)d_in[i];
        else if (in_sizes[i] == CC*DD)     text = (const float*)d_in[i];
    }
    float* out = (float*)d_out;

    cudaFuncSetAttribute(gemm_softmax_kernel,
                         cudaFuncAttributeMaxDynamicSharedMemorySize, SM_DYN);

    const int nwarps = BB*NN + CC + BB;
    convert_kernel<<<(nwarps*32 + 255)/256, 256>>>(vcls, vp, text);
    affg_kernel<<<BB, 512>>>(vcls, text, out);
    gemm_softmax_kernel<<<1024, 512, SM_DYN>>>();
    topk_kernel<<<(BB*CC*32 + 255)/256, 256>>>(out);
}

// round 6
// speedup vs baseline: 3.7617x; 1.0408x over previous
#include <cuda_runtime.h>
#include <cuda_fp16.h>
#include <math.h>
#include <stdint.h>

#define BB 64
#define NN 1024
#define DD 512
#define CC 512
#define KTOP 16
#define INV_TEMP (1.0f/0.07f)

// ---------------- scratch (device globals: no allocations allowed) ----------
__device__ __half g_aff[(size_t)BB * CC * NN];    // [b][c][n] normalized softmax p (fp16)
__device__ float g_rnp[BB * NN];                  // 1/||patch||
__device__ float g_rnt[CC];
__device__ float g_rnc[BB];
__device__ __half g_vph[(size_t)BB*NN*DD];        // patches fp16
__device__ __half g_txh[(size_t)CC*DD];           // text fp16

// ================= helpers ====================================================
static __device__ __forceinline__ uint32_t smem_u32(const void* p){
    uint32_t a;
    asm("{ .reg .u64 t; cvta.to.shared.u64 t, %1; cvt.u32.u64 %0, t; }" : "=r"(a) : "l"(p));
    return a;
}
static __device__ __forceinline__ void cpasync16(uint32_t dst, const void* src){
    asm volatile("cp.async.cg.shared.global [%0], [%1], 16;" :: "r"(dst), "l"(src) : "memory");
}
static __device__ __forceinline__ uint32_t swz(uint32_t o){ return o ^ ((o >> 3) & 0x70u); }

static __device__ __forceinline__ void ldsm4(uint32_t &r0, uint32_t &r1,
                                             uint32_t &r2, uint32_t &r3, uint32_t addr){
    asm volatile("ldmatrix.sync.aligned.m8n8.x4.shared.b16 {%0,%1,%2,%3}, [%4];"
        : "=r"(r0), "=r"(r1), "=r"(r2), "=r"(r3) : "r"(addr));
}
static __device__ __forceinline__ void mma16816(float* d, const uint32_t* a,
                                                uint32_t b0, uint32_t b1){
    asm volatile("mma.sync.aligned.m16n8k16.row.col.f32.f16.f16.f32 "
        "{%0,%1,%2,%3}, {%4,%5,%6,%7}, {%8,%9}, {%0,%1,%2,%3};"
        : "+f"(d[0]), "+f"(d[1]), "+f"(d[2]), "+f"(d[3])
        : "r"(a[0]), "r"(a[1]), "r"(a[2]), "r"(a[3]), "r"(b0), "r"(b1));
}

// ================= kernel 1: convert to fp16 + L2 norms ======================
__global__ void convert_kernel(const float* __restrict__ vcls,
                               const float* __restrict__ vp,
                               const float* __restrict__ text){
    int w    = (blockIdx.x * blockDim.x + threadIdx.x) >> 5;
    int lane = threadIdx.x & 31;
    const int NW = BB*NN + CC + BB;
    if (w >= NW) return;
    const float* src; __half* hi = nullptr; float* rdst;
    if (w < BB*NN){ src = vp + (size_t)w*DD; hi = g_vph + (size_t)w*DD; rdst = g_rnp + w; }
    else if (w < BB*NN + CC){ int t = w - BB*NN; src = text + (size_t)t*DD; hi = g_txh + (size_t)t*DD; rdst = g_rnt + t; }
    else { int ci = w - BB*NN - CC; src = vcls + (size_t)ci*DD; rdst = g_rnc + ci; }
    float ss = 0.f;
    #pragma unroll
    for (int j = 0; j < 4; j++){
        int o = (j*32 + lane) * 4;
        float4 v = *reinterpret_cast<const float4*>(src + o);
        ss += v.x*v.x + v.y*v.y + v.z*v.z + v.w*v.w;
        if (hi){
            union { __half2 h2[2]; uint2 u; } P;
            P.h2[0] = __floats2half2_rn(v.x, v.y);
            P.h2[1] = __floats2half2_rn(v.z, v.w);
            *reinterpret_cast<uint2*>(hi + o) = P.u;
        }
    }
    #pragma unroll
    for (int off = 16; off; off >>= 1) ss += __shfl_xor_sync(0xffffffffu, ss, off);
    if (lane == 0) *rdst = 1.0f / fmaxf(sqrtf(ss), 1e-12f);
}

// ================= kernel 2: global affinity, writes 0.3*softmax ============
__global__ __launch_bounds__(512) void affg_kernel(const float* __restrict__ vcls,
                                                   const float* __restrict__ text,
                                                   float* __restrict__ out){
    __shared__ float sv[DD];
    __shared__ float red[16];
    int b = blockIdx.x, tid = threadIdx.x;
    sv[tid] = vcls[b*DD + tid];
    __syncthreads();
    const float* t = text + (size_t)tid * DD;
    float dot = 0.f;
    #pragma unroll 4
    for (int k = 0; k < DD; k += 4){
        float4 v = *reinterpret_cast<const float4*>(t + k);
        dot += v.x*sv[k] + v.y*sv[k+1] + v.z*sv[k+2] + v.w*sv[k+3];
    }
    float logit = dot * g_rnc[b] * g_rnt[tid] * INV_TEMP;
    int lane = tid & 31, wid = tid >> 5;
    float m = logit;
    #pragma unroll
    for (int off = 16; off; off >>= 1) m = fmaxf(m, __shfl_xor_sync(0xffffffffu, m, off));
    if (lane == 0) red[wid] = m;
    __syncthreads();
    float bm = red[0];
    #pragma unroll
    for (int i = 1; i < 16; i++) bm = fmaxf(bm, red[i]);
    __syncthreads();
    float e = __expf(logit - bm);
    float s = e;
    #pragma unroll
    for (int off = 16; off; off >>= 1) s += __shfl_xor_sync(0xffffffffu, s, off);
    if (lane == 0) red[wid] = s;
    __syncthreads();
    float bs = 0.f;
    #pragma unroll
    for (int i = 0; i < 16; i++) bs += red[i];
    out[b*CC + tid] = 0.3f * e / bs;
}

// ================= kernel 3: fp16 HMMA GEMM + fused softmax ==================
// CTA: 64 patches x 512 classes, 256 threads (8 warps, nw=wid).
// Warp tile 64 rows x 64 cols (acc 128 regs). K = 512 (8 iters of kc=64).
#define SM_A0   0u
#define SM_A1   8192u
#define SM_B0   16384u
#define SM_B1   81920u
#define SM_AUX  147456u
#define SM_DYN  (152576u + 1024u)

static __device__ __forceinline__ void issue_loads(int kt, uint32_t a_dst, uint32_t b_dst,
                                                   int pb, int tid){
    const __half* Ab = g_vph + ((size_t)pb * 64) * DD + kt * 64;
    const __half* Bb = g_txh + kt * 64;
    #pragma unroll
    for (int t = 0; t < 2; t++){   // A: 64 rows x 128B = 512 chunks
        int g = tid + t*256; int row = g >> 3; int c16 = g & 7;
        cpasync16(a_dst + swz(row*128 + c16*16), Ab + (size_t)row*DD + c16*8);
    }
    #pragma unroll
    for (int t = 0; t < 16; t++){  // B: 512 rows x 128B = 4096 chunks
        int g = tid + t*256; int row = g >> 3; int c16 = g & 7;
        cpasync16(b_dst + swz(row*128 + c16*16), Bb + (size_t)row*DD + c16*8);
    }
    asm volatile("cp.async.commit_group;" ::: "memory");
}

__global__ __launch_bounds__(256, 1) void gemm_softmax_kernel(){
    extern __shared__ __align__(16) char dsm[];
    const uint32_t raw  = smem_u32(dsm);
    const uint32_t base = (raw + 1023u) & ~1023u;
    char* bp = dsm + (base - raw);

    const int tid = threadIdx.x;
    const int pb  = blockIdx.x;          // 0..1023
    const int b   = pb >> 4;
    const int nt  = pb & 15;

    const uint32_t ab[2]   = { base + SM_A0, base + SM_A1 };
    const uint32_t bbuf[2] = { base + SM_B0, base + SM_B1 };
    float* s_t    = reinterpret_cast<float*>(bp);                    // 512*68 f (overlays A/B)
    float* s_rnt  = reinterpret_cast<float*>(bp + SM_AUX);           // 512 f
    float* s_rnp  = reinterpret_cast<float*>(bp + SM_AUX + 2048);    // 64 f
    float* s_red  = reinterpret_cast<float*>(bp + SM_AUX + 2304);    // 64*8 f
    float* s_gmax = reinterpret_cast<float*>(bp + SM_AUX + 4352);    // 64 f
    float* s_rzv  = reinterpret_cast<float*>(bp + SM_AUX + 4608);    // 64 f

    const int wid  = tid >> 5;           // 0..7 = n-warp
    const int lane = tid & 31;
    const int nw   = wid;
    const int gid  = lane >> 2;          // row group 0..7
    const int tig  = lane & 3;

    if (tid < 256){ s_rnt[tid] = g_rnt[tid]; s_rnt[tid+256] = g_rnt[tid+256]; }
    if (tid < 64)  s_rnp[tid] = g_rnp[pb*64 + tid];

    issue_loads(0, ab[0], bbuf[0], pb, tid);
    issue_loads(1, ab[1], bbuf[1], pb, tid);

    // ldmatrix lane addressing (canonical x4 fragment order)
    const int lr = (lane & 7) + ((lane >> 3) & 1) * 8;   // row within 16
    const int lk = (lane >> 4) * 16;                     // 16B col half

    float acc[4][8][4];
    #pragma unroll
    for (int mi = 0; mi < 4; mi++)
        #pragma unroll
        for (int j = 0; j < 8; j++)
            #pragma unroll
            for (int v = 0; v < 4; v++) acc[mi][j][v] = 0.f;

    for (int it = 0; it < 8; ++it){
        const int cur = it & 1;
        if (it == 7) asm volatile("cp.async.wait_group 0;" ::: "memory");
        else         asm volatile("cp.async.wait_group 1;" ::: "memory");
        __syncthreads();

        const uint32_t abase = ab[cur];
        const uint32_t bbase = bbuf[cur];
        #pragma unroll
        for (int ks = 0; ks < 4; ks++){
            uint32_t af[4][4];
            #pragma unroll
            for (int mi = 0; mi < 4; mi++){
                int r = mi*16 + lr;
                ldsm4(af[mi][0], af[mi][1], af[mi][2], af[mi][3],
                      abase + swz((uint32_t)(r*128 + ks*32 + lk)));
            }
            uint32_t bf[4][4];
            #pragma unroll
            for (int jj = 0; jj < 4; jj++){
                int r = nw*64 + jj*16 + lr;
                ldsm4(bf[jj][0], bf[jj][1], bf[jj][2], bf[jj][3],
                      bbase + swz((uint32_t)(r*128 + ks*32 + lk)));
            }
            #pragma unroll
            for (int mi = 0; mi < 4; mi++)
                #pragma unroll
                for (int j = 0; j < 8; j++)
                    mma16816(acc[mi][j], af[mi], bf[j>>1][j&1], bf[j>>1][(j&1)+2]);
        }
        __syncthreads();
        if (it + 2 < 8) issue_loads(it + 2, ab[cur], bbuf[cur], pb, tid);
    }

    // ---- epilogue: scale, softmax over full 512 cols, normalized fp16 store
    float rs[4][2], rt[8][2];
    #pragma unroll
    for (int mi = 0; mi < 4; mi++)
        #pragma unroll
        for (int h = 0; h < 2; h++)
            rs[mi][h] = s_rnp[mi*16 + h*8 + gid] * INV_TEMP;
    #pragma unroll
    for (int j = 0; j < 8; j++){
        int c0 = nw*64 + j*8 + tig*2;
        rt[j][0] = s_rnt[c0]; rt[j][1] = s_rnt[c0+1];
    }
    #pragma unroll
    for (int mi = 0; mi < 4; mi++)
        #pragma unroll
        for (int j = 0; j < 8; j++)
            #pragma unroll
            for (int v = 0; v < 4; v++)
                acc[mi][j][v] *= rs[mi][v>>1] * rt[j][v&1];

    // per-row max (warp slice over its 64 cols), quad shuffle, 8-warp smem reduce
    #pragma unroll
    for (int mi = 0; mi < 4; mi++)
        #pragma unroll
        for (int h = 0; h < 2; h++){
            float mx = -3.0e38f;
            #pragma unroll
            for (int j = 0; j < 8; j++)
                mx = fmaxf(mx, fmaxf(acc[mi][j][2*h], acc[mi][j][2*h+1]));
            mx = fmaxf(mx, __shfl_xor_sync(0xffffffffu, mx, 1));
            mx = fmaxf(mx, __shfl_xor_sync(0xffffffffu, mx, 2));
            if (tig == 0) s_red[(mi*16 + h*8 + gid)*8 + nw] = mx;
        }
    __syncthreads();
    if (tid < 64){
        float m = s_red[tid*8];
        #pragma unroll
        for (int k = 1; k < 8; k++) m = fmaxf(m, s_red[tid*8 + k]);
        s_gmax[tid] = m;
    }
    __syncthreads();

    // exp + row sum
    #pragma unroll
    for (int mi = 0; mi < 4; mi++)
        #pragma unroll
        for (int h = 0; h < 2; h++){
            float gm = s_gmax[mi*16 + h*8 + gid];
            float sm = 0.f;
            #pragma unroll
            for (int j = 0; j < 8; j++){
                float e0 = __expf(acc[mi][j][2*h]   - gm);
                float e1 = __expf(acc[mi][j][2*h+1] - gm);
                acc[mi][j][2*h] = e0; acc[mi][j][2*h+1] = e1;
                sm += e0 + e1;
            }
            sm += __shfl_xor_sync(0xffffffffu, sm, 1);
            sm += __shfl_xor_sync(0xffffffffu, sm, 2);
            if (tig == 0) s_red[(mi*16 + h*8 + gid)*8 + nw] = sm;
        }
    __syncthreads();
    if (tid < 64){
        float s = 0.f;
        #pragma unroll
        for (int k = 0; k < 8; k++) s += s_red[tid*8 + k];
        s_rzv[tid] = 1.0f / s;
    }
    __syncthreads();

    // normalized transposed store into padded smem [c][n], stride 68
    #pragma unroll
    for (int mi = 0; mi < 4; mi++)
        #pragma unroll
        for (int j = 0; j < 8; j++)
            #pragma unroll
            for (int v = 0; v < 4; v++){
                int col = nw*64 + j*8 + tig*2 + (v&1);
                int row = mi*16 + (v>>1)*8 + gid;
                s_t[col*68 + row] = acc[mi][j][v] * s_rzv[row];
            }
    __syncthreads();

    // coalesced fp16 copy-out: g_aff[b][c][nt*64 + n] as half2
    __half* obase = g_aff + (size_t)b * CC * NN + (size_t)nt * 64;
    const int cpart = tid >> 5;           // 0..7
    const int np    = tid & 31;           // half2 index within 64 n
    #pragma unroll 4
    for (int itc = 0; itc < 64; itc++){
        int c = itc*8 + cpart;
        __half2 h = __floats2half2_rn(s_t[c*68 + np*2], s_t[c*68 + np*2 + 1]);
        *reinterpret_cast<__half2*>(obase + (size_t)c * NN + np*2) = h;
    }
}

// ================= kernel 4: top-16 over N per (b,c), blend ==================
__global__ void topk_kernel(float* __restrict__ out){
    int w    = (blockIdx.x * blockDim.x + threadIdx.x) >> 5;  // b*512 + c
    int lane = threadIdx.x & 31;
    if (w >= BB*CC) return;
    const uint4* p = reinterpret_cast<const uint4*>(g_aff + (size_t)w * NN);

    // 1024 halves / 32 lanes = 32 per lane = 4 uint4 loads (8 halves each)
    unsigned v[32], cm[8];
    #pragma unroll
    for (int j = 0; j < 4; j++){
        uint4 q = p[j*32 + lane];
        unsigned r[4] = {q.x, q.y, q.z, q.w};
        #pragma unroll
        for (int t = 0; t < 4; t++){
            v[8*j + 2*t]     = r[t] & 0xFFFFu;
            v[8*j + 2*t + 1] = r[t] >> 16;
        }
        unsigned m0 = v[8*j]   > v[8*j+1] ? v[8*j]   : v[8*j+1];
        unsigned m1 = v[8*j+2] > v[8*j+3] ? v[8*j+2] : v[8*j+3];
        unsigned m2 = v[8*j+4] > v[8*j+5] ? v[8*j+4] : v[8*j+5];
        unsigned m3 = v[8*j+6] > v[8*j+7] ? v[8*j+6] : v[8*j+7];
        unsigned a = m0 > m1 ? m0 : m1;
        unsigned c2 = m2 > m3 ? m2 : m3;
        cm[2*j]   = a;          // chunk of 4: v[8j..8j+3]
        cm[2*j+1] = c2;         // chunk of 4: v[8j+4..8j+7]
        cm[2*j]   = m0 > m1 ? m0 : m1;
        cm[2*j+1] = m2 > m3 ? m2 : m3;
    }
    unsigned lm = 0; int lc = 0;
    #pragma unroll
    for (int j = 0; j < 8; j++) if (cm[j] > lm){ lm = cm[j]; lc = j; }

    float sum = 0.f;
    #pragma unroll
    for (int it = 0; it < KTOP; ++it){
        unsigned m;
        asm("redux.sync.max.u32 %0, %1, 0xffffffff;" : "=r"(m) : "r"(lm));
        __half_raw hr; hr.x = (unsigned short)m;
        sum += __half2float(*reinterpret_cast<__half*>(&hr));
        unsigned msk = __ballot_sync(0xffffffffu, lm == m);
        if (lane == __ffs(msk) - 1){
            #pragma unroll
            for (int j = 0; j < 8; j++) if (j == lc){
                bool done = false;
                #pragma unroll
                for (int q = 0; q < 4; q++){
                    if (!done && v[4*j+q] == m){ v[4*j+q] = 0u; done = true; }
                }
                unsigned a = v[4*j] > v[4*j+1] ? v[4*j] : v[4*j+1];
                unsigned c2 = v[4*j+2] > v[4*j+3] ? v[4*j+2] : v[4*j+3];
                cm[j] = a > c2 ? a : c2;
            }
            lm = 0; lc = 0;
            #pragma unroll
            for (int j = 0; j < 8; j++) if (cm[j] > lm){ lm = cm[j]; lc = j; }
        }
    }
    if (lane == 0) out[w] += 0.7f * (sum * (1.0f / (float)KTOP));
}

// ================= launch =====================================================
extern "C" void kernel_launch(void* const* d_in, const int* in_sizes, int n_in,
                              void* d_out, int out_size){
    const float* vcls = nullptr;
    const float* vp   = nullptr;
    const float* text = nullptr;
    for (int i = 0; i < n_in; i++){
        if      (in_sizes[i] == BB*DD)     vcls = (const float*)d_in[i];
        else if (in_sizes[i] == BB*NN*DD)  vp   = (const float*)d_in[i];
        else if (in_sizes[i] == CC*DD)     text = (const float*)d_in[i];
    }
    float* out = (float*)d_out;

    cudaFuncSetAttribute(gemm_softmax_kernel,
                         cudaFuncAttributeMaxDynamicSharedMemorySize, SM_DYN);

    const int nwarps = BB*NN + CC + BB;
    convert_kernel<<<(nwarps*32 + 255)/256, 256>>>(vcls, vp, text);
    affg_kernel<<<BB, 512>>>(vcls, text, out);
    gemm_softmax_kernel<<<1024, 256, SM_DYN>>>();
    topk_kernel<<<(BB*CC*32 + 255)/256, 256>>>(out);
}

// round 7
// speedup vs baseline: 3.9413x; 1.0478x over previous
#include <cuda_runtime.h>
#include <cuda_fp16.h>
#include <math.h>
#include <stdint.h>

#define BB 64
#define NN 1024
#define DD 512
#define CC 512
#define KTOP 16
#define INV_TEMP (1.0f/0.07f)

// ---------------- scratch (device globals: no allocations allowed) ----------
__device__ __half g_aff[(size_t)BB * CC * NN];    // [b][c][n] normalized softmax p (fp16)
__device__ float g_rnt[CC];
__device__ float g_rnc[BB];
__device__ __half g_txh[(size_t)CC*DD];           // text fp16

// ================= helpers ====================================================
static __device__ __forceinline__ uint32_t smem_u32(const void* p){
    uint32_t a;
    asm("{ .reg .u64 t; cvta.to.shared.u64 t, %1; cvt.u32.u64 %0, t; }" : "=r"(a) : "l"(p));
    return a;
}
static __device__ __forceinline__ void cpasync16(uint32_t dst, const void* src){
    asm volatile("cp.async.cg.shared.global [%0], [%1], 16;" :: "r"(dst), "l"(src) : "memory");
}
static __device__ __forceinline__ uint32_t swz(uint32_t o){ return o ^ ((o >> 3) & 0x70u); }

static __device__ __forceinline__ void ldsm4(uint32_t &r0, uint32_t &r1,
                                             uint32_t &r2, uint32_t &r3, uint32_t addr){
    asm volatile("ldmatrix.sync.aligned.m8n8.x4.shared.b16 {%0,%1,%2,%3}, [%4];"
        : "=r"(r0), "=r"(r1), "=r"(r2), "=r"(r3) : "r"(addr));
}
static __device__ __forceinline__ void mma16816(float* d, const uint32_t* a,
                                                uint32_t b0, uint32_t b1){
    asm volatile("mma.sync.aligned.m16n8k16.row.col.f32.f16.f16.f32 "
        "{%0,%1,%2,%3}, {%4,%5,%6,%7}, {%8,%9}, {%0,%1,%2,%3};"
        : "+f"(d[0]), "+f"(d[1]), "+f"(d[2]), "+f"(d[3])
        : "r"(a[0]), "r"(a[1]), "r"(a[2]), "r"(a[3]), "r"(b0), "r"(b1));
}
static __device__ __forceinline__ void sts128(uint32_t addr, uint32_t a, uint32_t b,
                                              uint32_t c, uint32_t d){
    asm volatile("st.shared.v4.b32 [%0], {%1,%2,%3,%4};"
        :: "r"(addr), "r"(a), "r"(b), "r"(c), "r"(d) : "memory");
}

// ================= kernel 1: text fp16 convert + text/cls L2 norms ===========
__global__ void convert_kernel(const float* __restrict__ vcls,
                               const float* __restrict__ text){
    int w    = (blockIdx.x * blockDim.x + threadIdx.x) >> 5;
    int lane = threadIdx.x & 31;
    const int NW = CC + BB;
    if (w >= NW) return;
    const float* src; __half* hi = nullptr; float* rdst;
    if (w < CC){ src = text + (size_t)w*DD; hi = g_txh + (size_t)w*DD; rdst = g_rnt + w; }
    else       { int ci = w - CC; src = vcls + (size_t)ci*DD; rdst = g_rnc + ci; }
    float ss = 0.f;
    #pragma unroll
    for (int j = 0; j < 4; j++){
        int o = (j*32 + lane) * 4;
        float4 v = *reinterpret_cast<const float4*>(src + o);
        ss += v.x*v.x + v.y*v.y + v.z*v.z + v.w*v.w;
        if (hi){
            union { __half2 h2[2]; uint2 u; } P;
            P.h2[0] = __floats2half2_rn(v.x, v.y);
            P.h2[1] = __floats2half2_rn(v.z, v.w);
            *reinterpret_cast<uint2*>(hi + o) = P.u;
        }
    }
    #pragma unroll
    for (int off = 16; off; off >>= 1) ss += __shfl_xor_sync(0xffffffffu, ss, off);
    if (lane == 0) *rdst = 1.0f / fmaxf(sqrtf(ss), 1e-12f);
}

// ================= kernel 2: global affinity, writes 0.3*softmax ============
__global__ __launch_bounds__(512) void affg_kernel(const float* __restrict__ vcls,
                                                   const float* __restrict__ text,
                                                   float* __restrict__ out){
    __shared__ float sv[DD];
    __shared__ float red[16];
    int b = blockIdx.x, tid = threadIdx.x;
    sv[tid] = vcls[b*DD + tid];
    __syncthreads();
    const float* t = text + (size_t)tid * DD;
    float dot = 0.f;
    #pragma unroll 4
    for (int k = 0; k < DD; k += 4){
        float4 v = *reinterpret_cast<const float4*>(t + k);
        dot += v.x*sv[k] + v.y*sv[k+1] + v.z*sv[k+2] + v.w*sv[k+3];
    }
    float logit = dot * g_rnc[b] * g_rnt[tid] * INV_TEMP;
    int lane = tid & 31, wid = tid >> 5;
    float m = logit;
    #pragma unroll
    for (int off = 16; off; off >>= 1) m = fmaxf(m, __shfl_xor_sync(0xffffffffu, m, off));
    if (lane == 0) red[wid] = m;
    __syncthreads();
    float bm = red[0];
    #pragma unroll
    for (int i = 1; i < 16; i++) bm = fmaxf(bm, red[i]);
    __syncthreads();
    float e = __expf(logit - bm);
    float s = e;
    #pragma unroll
    for (int off = 16; off; off >>= 1) s += __shfl_xor_sync(0xffffffffu, s, off);
    if (lane == 0) red[wid] = s;
    __syncthreads();
    float bs = 0.f;
    #pragma unroll
    for (int i = 0; i < 16; i++) bs += red[i];
    out[b*CC + tid] = 0.3f * e / bs;
}

// ================= kernel 3: fp16 HMMA GEMM (fused A convert+norm) ===========
// CTA: 64 patches x 512 classes, 256 threads (8 warps, nw=wid).
// A read from global f32, converted in-kernel; patch norms computed in-kernel.
#define SM_A0   0u
#define SM_A1   8192u
#define SM_B0   16384u
#define SM_B1   81920u
#define SM_AUX  147456u
#define SM_DYN  (152576u + 1024u)

static __device__ __forceinline__ void issueB(int kt, uint32_t b_dst, int tid){
    const __half* Bb = g_txh + kt * 64;
    #pragma unroll
    for (int t = 0; t < 16; t++){  // B: 512 rows x 128B = 4096 chunks
        int g = tid + t*256; int row = g >> 3; int c16 = g & 7;
        cpasync16(b_dst + swz(row*128 + c16*16), Bb + (size_t)row*DD + c16*8);
    }
    asm volatile("cp.async.commit_group;" ::: "memory");
}

static __device__ __forceinline__ void stsA(uint32_t abase, int row, int q,
                                            const float4* pf, float& ss){
    uint32_t h[8];
    #pragma unroll
    for (int i = 0; i < 4; i++){
        union { __half2 h2; uint32_t u; } P0, P1;
        P0.h2 = __floats2half2_rn(pf[i].x, pf[i].y);
        P1.h2 = __floats2half2_rn(pf[i].z, pf[i].w);
        h[2*i] = P0.u; h[2*i+1] = P1.u;
        ss += pf[i].x*pf[i].x + pf[i].y*pf[i].y + pf[i].z*pf[i].z + pf[i].w*pf[i].w;
    }
    uint32_t off = (uint32_t)(row*128 + q*32);
    sts128(abase + swz(off),      h[0], h[1], h[2], h[3]);
    sts128(abase + swz(off + 16), h[4], h[5], h[6], h[7]);
}

__global__ __launch_bounds__(256, 1) void gemm_softmax_kernel(const float* __restrict__ vp){
    extern __shared__ __align__(16) char dsm[];
    const uint32_t raw  = smem_u32(dsm);
    const uint32_t base = (raw + 1023u) & ~1023u;
    char* bp = dsm + (base - raw);

    const int tid = threadIdx.x;
    const int pb  = blockIdx.x;          // 0..1023
    const int b   = pb >> 4;
    const int nt  = pb & 15;

    const uint32_t ab[2]   = { base + SM_A0, base + SM_A1 };
    const uint32_t bbuf[2] = { base + SM_B0, base + SM_B1 };
    float* s_t    = reinterpret_cast<float*>(bp);                    // 512*68 f (overlays A/B)
    float* s_rnt  = reinterpret_cast<float*>(bp + SM_AUX);           // 512 f
    float* s_rnp  = reinterpret_cast<float*>(bp + SM_AUX + 2048);    // 64 f
    float* s_red  = reinterpret_cast<float*>(bp + SM_AUX + 2304);    // 64*8 f
    float* s_gmax = reinterpret_cast<float*>(bp + SM_AUX + 4352);    // 64 f
    float* s_rzv  = reinterpret_cast<float*>(bp + SM_AUX + 4608);    // 64 f

    const int wid  = tid >> 5;           // 0..7 = n-warp
    const int lane = tid & 31;
    const int nw   = wid;
    const int gid  = lane >> 2;          // row group 0..7
    const int tig  = lane & 3;

    s_rnt[tid] = g_rnt[tid]; s_rnt[tid+256] = g_rnt[tid+256];

    // A register prefetch: thread covers (row4, 16-float quarter q4)
    const int row4 = tid >> 2;
    const int q4   = tid & 3;
    const float* Ag = vp + ((size_t)(pb*64 + row4))*DD + q4*16;

    float4 pf[4];
    #pragma unroll
    for (int i = 0; i < 4; i++) pf[i] = *reinterpret_cast<const float4*>(Ag + i*4);

    issueB(0, bbuf[0], tid);
    issueB(1, bbuf[1], tid);

    float ss = 0.f;
    stsA(ab[0], row4, q4, pf, ss);                       // A tile for kt=0
    #pragma unroll
    for (int i = 0; i < 4; i++) pf[i] = *reinterpret_cast<const float4*>(Ag + 64 + i*4);

    // ldmatrix lane addressing (canonical x4 fragment order)
    const int lr = (lane & 7) + ((lane >> 3) & 1) * 8;   // row within 16
    const int lk = (lane >> 4) * 16;                     // 16B col half

    float acc[4][8][4];
    #pragma unroll
    for (int mi = 0; mi < 4; mi++)
        #pragma unroll
        for (int j = 0; j < 8; j++)
            #pragma unroll
            for (int v = 0; v < 4; v++) acc[mi][j][v] = 0.f;

    for (int it = 0; it < 8; ++it){
        const int cur = it & 1;
        if (it == 7) asm volatile("cp.async.wait_group 0;" ::: "memory");
        else         asm volatile("cp.async.wait_group 1;" ::: "memory");
        __syncthreads();

        const uint32_t abase = ab[cur];
        const uint32_t bbase = bbuf[cur];
        #pragma unroll
        for (int ks = 0; ks < 4; ks++){
            uint32_t af[4][4];
            #pragma unroll
            for (int mi = 0; mi < 4; mi++){
                int r = mi*16 + lr;
                ldsm4(af[mi][0], af[mi][1], af[mi][2], af[mi][3],
                      abase + swz((uint32_t)(r*128 + ks*32 + lk)));
            }
            uint32_t bf[4][4];
            #pragma unroll
            for (int jj = 0; jj < 4; jj++){
                int r = nw*64 + jj*16 + lr;
                ldsm4(bf[jj][0], bf[jj][1], bf[jj][2], bf[jj][3],
                      bbase + swz((uint32_t)(r*128 + ks*32 + lk)));
            }
            #pragma unroll
            for (int mi = 0; mi < 4; mi++)
                #pragma unroll
                for (int j = 0; j < 8; j++)
                    mma16816(acc[mi][j], af[mi], bf[j>>1][j&1], bf[j>>1][(j&1)+2]);
        }
        __syncthreads();
        if (it + 1 < 8) stsA(ab[(it+1)&1], row4, q4, pf, ss);   // A tile for kt=it+1
        if (it + 2 < 8){
            #pragma unroll
            for (int i = 0; i < 4; i++)
                pf[i] = *reinterpret_cast<const float4*>(Ag + (it+2)*64 + i*4);
            issueB(it + 2, bbuf[cur], tid);
        }
    }

    // patch norms: quad-reduce sumsq (threads row4*4+q4 are consecutive)
    ss += __shfl_xor_sync(0xffffffffu, ss, 1);
    ss += __shfl_xor_sync(0xffffffffu, ss, 2);
    if (q4 == 0) s_rnp[row4] = 1.0f / fmaxf(sqrtf(ss), 1e-12f);
    __syncthreads();

    // ---- epilogue: scale, softmax over full 512 cols, normalized fp16 store
    float rs[4][2], rt[8][2];
    #pragma unroll
    for (int mi = 0; mi < 4; mi++)
        #pragma unroll
        for (int h = 0; h < 2; h++)
            rs[mi][h] = s_rnp[mi*16 + h*8 + gid] * INV_TEMP;
    #pragma unroll
    for (int j = 0; j < 8; j++){
        int c0 = nw*64 + j*8 + tig*2;
        rt[j][0] = s_rnt[c0]; rt[j][1] = s_rnt[c0+1];
    }
    #pragma unroll
    for (int mi = 0; mi < 4; mi++)
        #pragma unroll
        for (int j = 0; j < 8; j++)
            #pragma unroll
            for (int v = 0; v < 4; v++)
                acc[mi][j][v] *= rs[mi][v>>1] * rt[j][v&1];

    // per-row max (warp slice over its 64 cols), quad shuffle, 8-warp smem reduce
    #pragma unroll
    for (int mi = 0; mi < 4; mi++)
        #pragma unroll
        for (int h = 0; h < 2; h++){
            float mx = -3.0e38f;
            #pragma unroll
            for (int j = 0; j < 8; j++)
                mx = fmaxf(mx, fmaxf(acc[mi][j][2*h], acc[mi][j][2*h+1]));
            mx = fmaxf(mx, __shfl_xor_sync(0xffffffffu, mx, 1));
            mx = fmaxf(mx, __shfl_xor_sync(0xffffffffu, mx, 2));
            if (tig == 0) s_red[(mi*16 + h*8 + gid)*8 + nw] = mx;
        }
    __syncthreads();
    if (tid < 64){
        float m = s_red[tid*8];
        #pragma unroll
        for (int k = 1; k < 8; k++) m = fmaxf(m, s_red[tid*8 + k]);
        s_gmax[tid] = m;
    }
    __syncthreads();

    // exp + row sum
    #pragma unroll
    for (int mi = 0; mi < 4; mi++)
        #pragma unroll
        for (int h = 0; h < 2; h++){
            float gm = s_gmax[mi*16 + h*8 + gid];
            float sm = 0.f;
            #pragma unroll
            for (int j = 0; j < 8; j++){
                float e0 = __expf(acc[mi][j][2*h]   - gm);
                float e1 = __expf(acc[mi][j][2*h+1] - gm);
                acc[mi][j][2*h] = e0; acc[mi][j][2*h+1] = e1;
                sm += e0 + e1;
            }
            sm += __shfl_xor_sync(0xffffffffu, sm, 1);
            sm += __shfl_xor_sync(0xffffffffu, sm, 2);
            if (tig == 0) s_red[(mi*16 + h*8 + gid)*8 + nw] = sm;
        }
    __syncthreads();
    if (tid < 64){
        float s = 0.f;
        #pragma unroll
        for (int k = 0; k < 8; k++) s += s_red[tid*8 + k];
        s_rzv[tid] = 1.0f / s;
    }
    __syncthreads();

    // normalized transposed store into padded smem [c][n], stride 68
    #pragma unroll
    for (int mi = 0; mi < 4; mi++)
        #pragma unroll
        for (int j = 0; j < 8; j++)
            #pragma unroll
            for (int v = 0; v < 4; v++){
                int col = nw*64 + j*8 + tig*2 + (v&1);
                int row = mi*16 + (v>>1)*8 + gid;
                s_t[col*68 + row] = acc[mi][j][v] * s_rzv[row];
            }
    __syncthreads();

    // coalesced fp16 copy-out: g_aff[b][c][nt*64 + n] as half2
    __half* obase = g_aff + (size_t)b * CC * NN + (size_t)nt * 64;
    const int cpart = tid >> 5;           // 0..7
    const int np    = tid & 31;           // half2 index within 64 n
    #pragma unroll 4
    for (int itc = 0; itc < 64; itc++){
        int c = itc*8 + cpart;
        __half2 h = __floats2half2_rn(s_t[c*68 + np*2], s_t[c*68 + np*2 + 1]);
        *reinterpret_cast<__half2*>(obase + (size_t)c * NN + np*2) = h;
    }
}

// ================= kernel 4: top-16 over N per (b,c), blend ==================
// key = (fp16bits << 16) | (lane << 3) | chunk : one redux gives value+owner+chunk
__global__ void topk_kernel(float* __restrict__ out){
    int w    = (blockIdx.x * blockDim.x + threadIdx.x) >> 5;  // b*512 + c
    int lane = threadIdx.x & 31;
    if (w >= BB*CC) return;
    const uint4* p = reinterpret_cast<const uint4*>(g_aff + (size_t)w * NN);

    unsigned v[32], ck[8];
    #pragma unroll
    for (int j = 0; j < 4; j++){
        uint4 q = p[j*32 + lane];
        v[8*j+0] = q.x & 0xFFFFu; v[8*j+1] = q.x >> 16;
        v[8*j+2] = q.y & 0xFFFFu; v[8*j+3] = q.y >> 16;
        v[8*j+4] = q.z & 0xFFFFu; v[8*j+5] = q.z >> 16;
        v[8*j+6] = q.w & 0xFFFFu; v[8*j+7] = q.w >> 16;
    }
    #pragma unroll
    for (int c = 0; c < 8; c++){
        unsigned m0 = v[4*c]   > v[4*c+1] ? v[4*c]   : v[4*c+1];
        unsigned m1 = v[4*c+2] > v[4*c+3] ? v[4*c+2] : v[4*c+3];
        unsigned mv = m0 > m1 ? m0 : m1;
        ck[c] = (mv << 16) | ((unsigned)lane << 3) | (unsigned)c;
    }
    unsigned lk = ck[0];
    #pragma unroll
    for (int c = 1; c < 8; c++) lk = ck[c] > lk ? ck[c] : lk;

    float sum = 0.f;
    #pragma unroll
    for (int it = 0; it < KTOP; ++it){
        unsigned m;
        asm("redux.sync.max.u32 %0, %1, 0xffffffff;" : "=r"(m) : "r"(lk));
        __half_raw hr; hr.x = (unsigned short)(m >> 16);
        sum += __half2float(*reinterpret_cast<__half*>(&hr));
        if (((m >> 3) & 31u) == (unsigned)lane){
            unsigned val = m >> 16;
            int oc = (int)(m & 7u);
            #pragma unroll
            for (int c = 0; c < 8; c++) if (c == oc){
                if      (v[4*c]   == val) v[4*c]   = 0u;
                else if (v[4*c+1] == val) v[4*c+1] = 0u;
                else if (v[4*c+2] == val) v[4*c+2] = 0u;
                else                      v[4*c+3] = 0u;
                unsigned m0 = v[4*c]   > v[4*c+1] ? v[4*c]   : v[4*c+1];
                unsigned m1 = v[4*c+2] > v[4*c+3] ? v[4*c+2] : v[4*c+3];
                unsigned mv = m0 > m1 ? m0 : m1;
                ck[c] = (mv << 16) | ((unsigned)lane << 3) | (unsigned)c;
            }
            lk = ck[0];
            #pragma unroll
            for (int c = 1; c < 8; c++) lk = ck[c] > lk ? ck[c] : lk;
        }
    }
    if (lane == 0) out[w] += 0.7f * (sum * (1.0f / (float)KTOP));
}

// ================= launch =====================================================
extern "C" void kernel_launch(void* const* d_in, const int* in_sizes, int n_in,
                              void* d_out, int out_size){
    const float* vcls = nullptr;
    const float* vp   = nullptr;
    const float* text = nullptr;
    for (int i = 0; i < n_in; i++){
        if      (in_sizes[i] == BB*DD)     vcls = (const float*)d_in[i];
        else if (in_sizes[i] == BB*NN*DD)  vp   = (const float*)d_in[i];
        else if (in_sizes[i] == CC*DD)     text = (const float*)d_in[i];
    }
    float* out = (float*)d_out;

    cudaFuncSetAttribute(gemm_softmax_kernel,
                         cudaFuncAttributeMaxDynamicSharedMemorySize, SM_DYN);

    const int nwarps = CC + BB;
    convert_kernel<<<(nwarps*32 + 255)/256, 256>>>(vcls, text);
    affg_kernel<<<BB, 512>>>(vcls, text, out);
    gemm_softmax_kernel<<<1024, 256, SM_DYN>>>(vp);
    topk_kernel<<<(BB*CC*32 + 255)/256, 256>>>(out);
}

// round 8
// speedup vs baseline: 4.0402x; 1.0251x over previous
#include <cuda_runtime.h>
#include <cuda_fp16.h>
#include <math.h>
#include <stdint.h>

#define BB 64
#define NN 1024
#define DD 512
#define CC 512
#define KTOP 16
#define INV_TEMP (1.0f/0.07f)

// ---------------- scratch (device globals: no allocations allowed) ----------
__device__ __half g_aff[(size_t)BB * CC * NN];    // [b][c][n] normalized softmax p (fp16)
__device__ float g_rnt[CC];
__device__ float g_rnc[BB];
__device__ __half g_txh[(size_t)CC*DD];           // text fp16

// ================= helpers ====================================================
static __device__ __forceinline__ uint32_t smem_u32(const void* p){
    uint32_t a;
    asm("{ .reg .u64 t; cvta.to.shared.u64 t, %1; cvt.u32.u64 %0, t; }" : "=r"(a) : "l"(p));
    return a;
}
static __device__ __forceinline__ void cpasync16(uint32_t dst, const void* src){
    asm volatile("cp.async.cg.shared.global [%0], [%1], 16;" :: "r"(dst), "l"(src) : "memory");
}
static __device__ __forceinline__ uint32_t swz(uint32_t o){ return o ^ ((o >> 3) & 0x70u); }

static __device__ __forceinline__ void ldsm4(uint32_t &r0, uint32_t &r1,
                                             uint32_t &r2, uint32_t &r3, uint32_t addr){
    asm volatile("ldmatrix.sync.aligned.m8n8.x4.shared.b16 {%0,%1,%2,%3}, [%4];"
        : "=r"(r0), "=r"(r1), "=r"(r2), "=r"(r3) : "r"(addr));
}
static __device__ __forceinline__ void mma16816(float* d, const uint32_t* a,
                                                uint32_t b0, uint32_t b1){
    asm volatile("mma.sync.aligned.m16n8k16.row.col.f32.f16.f16.f32 "
        "{%0,%1,%2,%3}, {%4,%5,%6,%7}, {%8,%9}, {%0,%1,%2,%3};"
        : "+f"(d[0]), "+f"(d[1]), "+f"(d[2]), "+f"(d[3])
        : "r"(a[0]), "r"(a[1]), "r"(a[2]), "r"(a[3]), "r"(b0), "r"(b1));
}

// ================= kernel 1: text fp16 convert + text/cls L2 norms ===========
__global__ void convert_kernel(const float* __restrict__ vcls,
                               const float* __restrict__ text){
    int w    = (blockIdx.x * blockDim.x + threadIdx.x) >> 5;
    int lane = threadIdx.x & 31;
    const int NW = CC + BB;
    if (w >= NW) return;
    const float* src; __half* hi = nullptr; float* rdst;
    if (w < CC){ src = text + (size_t)w*DD; hi = g_txh + (size_t)w*DD; rdst = g_rnt + w; }
    else       { int ci = w - CC; src = vcls + (size_t)ci*DD; rdst = g_rnc + ci; }
    float ss = 0.f;
    #pragma unroll
    for (int j = 0; j < 4; j++){
        int o = (j*32 + lane) * 4;
        float4 v = *reinterpret_cast<const float4*>(src + o);
        ss += v.x*v.x + v.y*v.y + v.z*v.z + v.w*v.w;
        if (hi){
            union { __half2 h2[2]; uint2 u; } P;
            P.h2[0] = __floats2half2_rn(v.x, v.y);
            P.h2[1] = __floats2half2_rn(v.z, v.w);
            *reinterpret_cast<uint2*>(hi + o) = P.u;
        }
    }
    #pragma unroll
    for (int off = 16; off; off >>= 1) ss += __shfl_xor_sync(0xffffffffu, ss, off);
    if (lane == 0) *rdst = 1.0f / fmaxf(sqrtf(ss), 1e-12f);
}

// ================= kernel 2: global affinity, writes 0.3*softmax ============
__global__ __launch_bounds__(512) void affg_kernel(const float* __restrict__ vcls,
                                                   const float* __restrict__ text,
                                                   float* __restrict__ out){
    __shared__ float sv[DD];
    __shared__ float red[16];
    int b = blockIdx.x, tid = threadIdx.x;
    sv[tid] = vcls[b*DD + tid];
    __syncthreads();
    const float* t = text + (size_t)tid * DD;
    float dot = 0.f;
    #pragma unroll 4
    for (int k = 0; k < DD; k += 4){
        float4 v = *reinterpret_cast<const float4*>(t + k);
        dot += v.x*sv[k] + v.y*sv[k+1] + v.z*sv[k+2] + v.w*sv[k+3];
    }
    float logit = dot * g_rnc[b] * g_rnt[tid] * INV_TEMP;
    int lane = tid & 31, wid = tid >> 5;
    float m = logit;
    #pragma unroll
    for (int off = 16; off; off >>= 1) m = fmaxf(m, __shfl_xor_sync(0xffffffffu, m, off));
    if (lane == 0) red[wid] = m;
    __syncthreads();
    float bm = red[0];
    #pragma unroll
    for (int i = 1; i < 16; i++) bm = fmaxf(bm, red[i]);
    __syncthreads();
    float e = __expf(logit - bm);
    float s = e;
    #pragma unroll
    for (int off = 16; off; off >>= 1) s += __shfl_xor_sync(0xffffffffu, s, off);
    if (lane == 0) red[wid] = s;
    __syncthreads();
    float bs = 0.f;
    #pragma unroll
    for (int i = 0; i < 16; i++) bs += red[i];
    out[b*CC + tid] = 0.3f * e / bs;
}

// ================= kernel 3: fp16 HMMA GEMM (fused A convert+norm) ===========
// CTA: 64 patches x 512 classes, 256 threads (8 warps, nw=wid).
// A read from global f32 COALESCED (c16=tid&15 contiguous), converted in-kernel.
#define SM_A0   0u
#define SM_A1   8192u
#define SM_B0   16384u
#define SM_B1   81920u
#define SM_AUX  147456u
#define SM_DYN  (152576u + 1024u)

static __device__ __forceinline__ void issueB(int kt, uint32_t b_dst, int tid){
    const __half* Bb = g_txh + kt * 64;
    #pragma unroll
    for (int t = 0; t < 16; t++){  // B: 512 rows x 128B = 4096 chunks
        int g = tid + t*256; int row = g >> 3; int c16 = g & 7;
        cpasync16(b_dst + swz(row*128 + c16*16), Bb + (size_t)row*DD + c16*8);
    }
    asm volatile("cp.async.commit_group;" ::: "memory");
}

// store 4 rows' worth of converted A (rows rbase+16i, 16B chunk c16 of f32 slab
// = 8B chunk of f16 tile row), accumulate per-row sumsq partials
static __device__ __forceinline__ void stsA(uint32_t abase, int rbase, int c16,
                                            const float4* pf, float* ss){
    #pragma unroll
    for (int i = 0; i < 4; i++){
        union { __half2 h2; uint32_t u; } P0, P1;
        P0.h2 = __floats2half2_rn(pf[i].x, pf[i].y);
        P1.h2 = __floats2half2_rn(pf[i].z, pf[i].w);
        ss[i] += pf[i].x*pf[i].x + pf[i].y*pf[i].y + pf[i].z*pf[i].z + pf[i].w*pf[i].w;
        uint32_t off = (uint32_t)((rbase + 16*i)*128 + c16*8);
        asm volatile("st.shared.v2.b32 [%0], {%1,%2};"
            :: "r"(abase + swz(off)), "r"(P0.u), "r"(P1.u) : "memory");
    }
}

__global__ __launch_bounds__(256, 1) void gemm_softmax_kernel(const float* __restrict__ vp){
    extern __shared__ __align__(16) char dsm[];
    const uint32_t raw  = smem_u32(dsm);
    const uint32_t base = (raw + 1023u) & ~1023u;
    char* bp = dsm + (base - raw);

    const int tid = threadIdx.x;
    const int pb  = blockIdx.x;          // 0..1023
    const int b   = pb >> 4;
    const int nt  = pb & 15;

    const uint32_t ab[2]   = { base + SM_A0, base + SM_A1 };
    const uint32_t bbuf[2] = { base + SM_B0, base + SM_B1 };
    float* s_t    = reinterpret_cast<float*>(bp);                    // 512*68 f (overlays A/B)
    float* s_rnt  = reinterpret_cast<float*>(bp + SM_AUX);           // 512 f
    float* s_rnp  = reinterpret_cast<float*>(bp + SM_AUX + 2048);    // 64 f
    float* s_red  = reinterpret_cast<float*>(bp + SM_AUX + 2304);    // 64*8 f
    float* s_gmax = reinterpret_cast<float*>(bp + SM_AUX + 4352);    // 64 f
    float* s_rzv  = reinterpret_cast<float*>(bp + SM_AUX + 4608);    // 64 f

    const int wid  = tid >> 5;           // 0..7 = n-warp
    const int lane = tid & 31;
    const int nw   = wid;
    const int gid  = lane >> 2;          // row group 0..7
    const int tig  = lane & 3;

    s_rnt[tid] = g_rnt[tid]; s_rnt[tid+256] = g_rnt[tid+256];

    // A coalesced prefetch: lane group covers a contiguous 256B row segment
    const int c16 = tid & 15;            // 16B chunk within 64-float slab row
    const int rb  = tid >> 4;            // base row 0..15 (rows rb+16i)
    const float* Ag = vp + ((size_t)(pb*64 + rb))*DD + c16*4;

    float4 pf[4];
    #pragma unroll
    for (int i = 0; i < 4; i++)
        pf[i] = *reinterpret_cast<const float4*>(Ag + (size_t)i*16*DD);

    issueB(0, bbuf[0], tid);
    issueB(1, bbuf[1], tid);

    float ss[4] = {0.f, 0.f, 0.f, 0.f};
    stsA(ab[0], rb, c16, pf, ss);                        // A tile for kt=0
    #pragma unroll
    for (int i = 0; i < 4; i++)
        pf[i] = *reinterpret_cast<const float4*>(Ag + (size_t)i*16*DD + 64);

    // ldmatrix lane addressing (canonical x4 fragment order)
    const int lr = (lane & 7) + ((lane >> 3) & 1) * 8;   // row within 16
    const int lk = (lane >> 4) * 16;                     // 16B col half

    float acc[4][8][4];
    #pragma unroll
    for (int mi = 0; mi < 4; mi++)
        #pragma unroll
        for (int j = 0; j < 8; j++)
            #pragma unroll
            for (int v = 0; v < 4; v++) acc[mi][j][v] = 0.f;

    for (int it = 0; it < 8; ++it){
        const int cur = it & 1;
        if (it == 7) asm volatile("cp.async.wait_group 0;" ::: "memory");
        else         asm volatile("cp.async.wait_group 1;" ::: "memory");
        __syncthreads();

        const uint32_t abase = ab[cur];
        const uint32_t bbase = bbuf[cur];
        #pragma unroll
        for (int ks = 0; ks < 4; ks++){
            uint32_t af[4][4];
            #pragma unroll
            for (int mi = 0; mi < 4; mi++){
                int r = mi*16 + lr;
                ldsm4(af[mi][0], af[mi][1], af[mi][2], af[mi][3],
                      abase + swz((uint32_t)(r*128 + ks*32 + lk)));
            }
            uint32_t bf[4][4];
            #pragma unroll
            for (int jj = 0; jj < 4; jj++){
                int r = nw*64 + jj*16 + lr;
                ldsm4(bf[jj][0], bf[jj][1], bf[jj][2], bf[jj][3],
                      bbase + swz((uint32_t)(r*128 + ks*32 + lk)));
            }
            #pragma unroll
            for (int mi = 0; mi < 4; mi++)
                #pragma unroll
                for (int j = 0; j < 8; j++)
                    mma16816(acc[mi][j], af[mi], bf[j>>1][j&1], bf[j>>1][(j&1)+2]);
        }
        __syncthreads();
        if (it + 1 < 8) stsA(ab[(it+1)&1], rb, c16, pf, ss);   // A tile for kt=it+1
        if (it + 2 < 8){
            #pragma unroll
            for (int i = 0; i < 4; i++)
                pf[i] = *reinterpret_cast<const float4*>(Ag + (size_t)i*16*DD + (it+2)*64);
            issueB(it + 2, bbuf[cur], tid);
        }
    }

    // patch norms: reduce sumsq over the 16-lane group sharing each row
    #pragma unroll
    for (int i = 0; i < 4; i++){
        float s = ss[i];
        s += __shfl_xor_sync(0xffffffffu, s, 1);
        s += __shfl_xor_sync(0xffffffffu, s, 2);
        s += __shfl_xor_sync(0xffffffffu, s, 4);
        s += __shfl_xor_sync(0xffffffffu, s, 8);
        if (c16 == 0) s_rnp[rb + 16*i] = 1.0f / fmaxf(sqrtf(s), 1e-12f);
    }
    __syncthreads();

    // ---- epilogue: scale, softmax over full 512 cols, normalized fp16 store
    float rs[4][2], rt[8][2];
    #pragma unroll
    for (int mi = 0; mi < 4; mi++)
        #pragma unroll
        for (int h = 0; h < 2; h++)
            rs[mi][h] = s_rnp[mi*16 + h*8 + gid] * INV_TEMP;
    #pragma unroll
    for (int j = 0; j < 8; j++){
        int c0 = nw*64 + j*8 + tig*2;
        rt[j][0] = s_rnt[c0]; rt[j][1] = s_rnt[c0+1];
    }
    #pragma unroll
    for (int mi = 0; mi < 4; mi++)
        #pragma unroll
        for (int j = 0; j < 8; j++)
            #pragma unroll
            for (int v = 0; v < 4; v++)
                acc[mi][j][v] *= rs[mi][v>>1] * rt[j][v&1];

    // per-row max (warp slice over its 64 cols), quad shuffle, 8-warp smem reduce
    #pragma unroll
    for (int mi = 0; mi < 4; mi++)
        #pragma unroll
        for (int h = 0; h < 2; h++){
            float mx = -3.0e38f;
            #pragma unroll
            for (int j = 0; j < 8; j++)
                mx = fmaxf(mx, fmaxf(acc[mi][j][2*h], acc[mi][j][2*h+1]));
            mx = fmaxf(mx, __shfl_xor_sync(0xffffffffu, mx, 1));
            mx = fmaxf(mx, __shfl_xor_sync(0xffffffffu, mx, 2));
            if (tig == 0) s_red[(mi*16 + h*8 + gid)*8 + nw] = mx;
        }
    __syncthreads();
    if (tid < 64){
        float m = s_red[tid*8];
        #pragma unroll
        for (int k = 1; k < 8; k++) m = fmaxf(m, s_red[tid*8 + k]);
        s_gmax[tid] = m;
    }
    __syncthreads();

    // exp + row sum
    #pragma unroll
    for (int mi = 0; mi < 4; mi++)
        #pragma unroll
        for (int h = 0; h < 2; h++){
            float gm = s_gmax[mi*16 + h*8 + gid];
            float sm = 0.f;
            #pragma unroll
            for (int j = 0; j < 8; j++){
                float e0 = __expf(acc[mi][j][2*h]   - gm);
                float e1 = __expf(acc[mi][j][2*h+1] - gm);
                acc[mi][j][2*h] = e0; acc[mi][j][2*h+1] = e1;
                sm += e0 + e1;
            }
            sm += __shfl_xor_sync(0xffffffffu, sm, 1);
            sm += __shfl_xor_sync(0xffffffffu, sm, 2);
            if (tig == 0) s_red[(mi*16 + h*8 + gid)*8 + nw] = sm;
        }
    __syncthreads();
    if (tid < 64){
        float s = 0.f;
        #pragma unroll
        for (int k = 0; k < 8; k++) s += s_red[tid*8 + k];
        s_rzv[tid] = 1.0f / s;
    }
    __syncthreads();

    // normalized transposed store into padded smem [c][n], stride 68
    #pragma unroll
    for (int mi = 0; mi < 4; mi++)
        #pragma unroll
        for (int j = 0; j < 8; j++)
            #pragma unroll
            for (int v = 0; v < 4; v++){
                int col = nw*64 + j*8 + tig*2 + (v&1);
                int row = mi*16 + (v>>1)*8 + gid;
                s_t[col*68 + row] = acc[mi][j][v] * s_rzv[row];
            }
    __syncthreads();

    // vectorized coalesced fp16 copy-out: g_aff[b][c][nt*64 + n]
    __half* obase = g_aff + (size_t)b * CC * NN + (size_t)nt * 64;
    const int cpart = tid >> 4;           // 0..15
    const int n4    = (tid & 15) * 4;     // 0..60
    #pragma unroll 4
    for (int itc = 0; itc < 32; itc++){
        int c = itc*16 + cpart;
        float4 f = *reinterpret_cast<const float4*>(&s_t[c*68 + n4]);
        union { __half2 h[2]; uint2 u; } U;
        U.h[0] = __floats2half2_rn(f.x, f.y);
        U.h[1] = __floats2half2_rn(f.z, f.w);
        *reinterpret_cast<uint2*>(obase + (size_t)c * NN + n4) = U.u;
    }
}

// ================= kernel 4: top-16 over N per (b,c), blend ==================
// key = (fp16bits << 16) | (lane << 3) | chunk : one redux gives value+owner+chunk
__global__ void topk_kernel(float* __restrict__ out){
    int w    = (blockIdx.x * blockDim.x + threadIdx.x) >> 5;  // b*512 + c
    int lane = threadIdx.x & 31;
    if (w >= BB*CC) return;
    const uint4* p = reinterpret_cast<const uint4*>(g_aff + (size_t)w * NN);

    unsigned v[32], ck[8];
    #pragma unroll
    for (int j = 0; j < 4; j++){
        uint4 q = p[j*32 + lane];
        v[8*j+0] = q.x & 0xFFFFu; v[8*j+1] = q.x >> 16;
        v[8*j+2] = q.y & 0xFFFFu; v[8*j+3] = q.y >> 16;
        v[8*j+4] = q.z & 0xFFFFu; v[8*j+5] = q.z >> 16;
        v[8*j+6] = q.w & 0xFFFFu; v[8*j+7] = q.w >> 16;
    }
    #pragma unroll
    for (int c = 0; c < 8; c++){
        unsigned m0 = v[4*c]   > v[4*c+1] ? v[4*c]   : v[4*c+1];
        unsigned m1 = v[4*c+2] > v[4*c+3] ? v[4*c+2] : v[4*c+3];
        unsigned mv = m0 > m1 ? m0 : m1;
        ck[c] = (mv << 16) | ((unsigned)lane << 3) | (unsigned)c;
    }
    unsigned lk = ck[0];
    #pragma unroll
    for (int c = 1; c < 8; c++) lk = ck[c] > lk ? ck[c] : lk;

    float sum = 0.f;
    #pragma unroll
    for (int it = 0; it < KTOP; ++it){
        unsigned m;
        asm("redux.sync.max.u32 %0, %1, 0xffffffff;" : "=r"(m) : "r"(lk));
        __half_raw hr; hr.x = (unsigned short)(m >> 16);
        sum += __half2float(*reinterpret_cast<__half*>(&hr));
        if (((m >> 3) & 31u) == (unsigned)lane){
            unsigned val = m >> 16;
            int oc = (int)(m & 7u);
            #pragma unroll
            for (int c = 0; c < 8; c++) if (c == oc){
                if      (v[4*c]   == val) v[4*c]   = 0u;
                else if (v[4*c+1] == val) v[4*c+1] = 0u;
                else if (v[4*c+2] == val) v[4*c+2] = 0u;
                else                      v[4*c+3] = 0u;
                unsigned m0 = v[4*c]   > v[4*c+1] ? v[4*c]   : v[4*c+1];
                unsigned m1 = v[4*c+2] > v[4*c+3] ? v[4*c+2] : v[4*c+3];
                unsigned mv = m0 > m1 ? m0 : m1;
                ck[c] = (mv << 16) | ((unsigned)lane << 3) | (unsigned)c;
            }
            lk = ck[0];
            #pragma unroll
            for (int c = 1; c < 8; c++) lk = ck[c] > lk ? ck[c] : lk;
        }
    }
    if (lane == 0) out[w] += 0.7f * (sum * (1.0f / (float)KTOP));
}

// ================= launch =====================================================
extern "C" void kernel_launch(void* const* d_in, const int* in_sizes, int n_in,
                              void* d_out, int out_size){
    const float* vcls = nullptr;
    const float* vp   = nullptr;
    const float* text = nullptr;
    for (int i = 0; i < n_in; i++){
        if      (in_sizes[i] == BB*DD)     vcls = (const float*)d_in[i];
        else if (in_sizes[i] == BB*NN*DD)  vp   = (const float*)d_in[i];
        else if (in_sizes[i] == CC*DD)     text = (const float*)d_in[i];
    }
    float* out = (float*)d_out;

    cudaFuncSetAttribute(gemm_softmax_kernel,
                         cudaFuncAttributeMaxDynamicSharedMemorySize, SM_DYN);

    const int nwarps = CC + BB;
    convert_kernel<<<(nwarps*32 + 255)/256, 256>>>(vcls, text);
    affg_kernel<<<BB, 512>>>(vcls, text, out);
    gemm_softmax_kernel<<<1024, 256, SM_DYN>>>(vp);
    topk_kernel<<<(BB*CC*32 + 255)/256, 256>>>(out);
}